// round 6
// baseline (speedup 1.0000x reference)
#include <cuda_runtime.h>
#include <cuda_bf16.h>
#include <cstdint>

// Problem constants
#define NB   32
#define NN   512
#define FIN  64
#define NH   4
#define HID  64
#define HF   256   // NH*HID
#define FOUT 64

typedef unsigned long long u64;

// Scratch (static device arrays; no allocation)
__device__ float g_H1[NB * NN * HF];       // layer-1 projections h = x@W1   (16 MB)
__device__ float g_E1s[NB * NN * NH];
__device__ float g_E1d[NB * NN * NH];
__device__ float g_H2[NB * NN * FOUT];     // layer-2 projections (4 MB)
__device__ float g_E2s[NB * NN];
__device__ float g_E2d[NB * NN];

// ---- packed f32x2 helpers ----
__device__ __forceinline__ void ffma2(u64& d, u64 a, u64 b) {
    asm("fma.rn.f32x2 %0, %1, %2, %0;" : "+l"(d) : "l"(a), "l"(b));
}
__device__ __forceinline__ u64 pack2(float x, float y) {
    u64 r; asm("mov.b64 %0, {%1, %2};" : "=l"(r) : "f"(x), "f"(y)); return r;
}
__device__ __forceinline__ float2 unpack2(u64 v) {
    float2 r; asm("mov.b64 {%0, %1}, %2;" : "=f"(r.x), "=f"(r.y) : "l"(v)); return r;
}

// ---------------------------------------------------------------------------
// Kernel A: H1 = x @ W1 plus e1_src/e1_dst. Grid (32, 16): batch, 32-row tile.
// Paired-row inner loop: 4 independent FFMA2 chains for ILP.
// ---------------------------------------------------------------------------
#define HS_STRIDE 264   // padded row stride for hs (breaks bank conflicts)

__global__ void __launch_bounds__(256, 2) kA(const float* __restrict__ x,
                                             const float* __restrict__ W1,
                                             const float* __restrict__ a1s,
                                             const float* __restrict__ a1d) {
    __shared__ __align__(16) float xs[32 * FIN];        // 8 KB
    __shared__ __align__(16) float hs[32 * HS_STRIDE];  // 33 KB
    __shared__ __align__(16) float av[2 * HF];          // a1s | a1d (2 KB)

    const int b = blockIdx.x, row0 = blockIdx.y * 32;
    const int t = threadIdx.x;

    const float* xp = x + ((size_t)(b * NN + row0)) * FIN;
    for (int i = t; i < 32 * FIN; i += 256) xs[i] = xp[i];
    {
        av[t]      = a1s[t];
        av[t + HF] = a1d[t];
    }

    // W1 column t, packed over k
    u64 w1p[32];
#pragma unroll
    for (int kk = 0; kk < 32; kk++)
        w1p[kk] = pack2(W1[(2 * kk) * HF + t], W1[(2 * kk + 1) * HF + t]);
    __syncthreads();

    float* H1p = g_H1 + ((size_t)(b * NN + row0)) * HF + t;
    const u64 z2 = pack2(0.f, 0.f);
    for (int r = 0; r < 32; r += 2) {
        const ulonglong2* xr0 = (const ulonglong2*)(xs + r * FIN);
        const ulonglong2* xr1 = (const ulonglong2*)(xs + (r + 1) * FIN);
        u64 aA0 = z2, aB0 = z2, aA1 = z2, aB1 = z2;
#pragma unroll
        for (int q = 0; q < 16; q++) {
            ulonglong2 x0 = xr0[q], x1 = xr1[q];
            ffma2(aA0, x0.x, w1p[2 * q]);
            ffma2(aB0, x0.y, w1p[2 * q + 1]);
            ffma2(aA1, x1.x, w1p[2 * q]);
            ffma2(aB1, x1.y, w1p[2 * q + 1]);
        }
        float2 fa0 = unpack2(aA0), fb0 = unpack2(aB0);
        float2 fa1 = unpack2(aA1), fb1 = unpack2(aB1);
        float acc0 = (fa0.x + fa0.y) + (fb0.x + fb0.y);
        float acc1 = (fa1.x + fa1.y) + (fb1.x + fb1.y);
        hs[r * HS_STRIDE + t]       = acc0;
        hs[(r + 1) * HS_STRIDE + t] = acc1;
        H1p[(size_t)r * HF]       = acc0;
        H1p[(size_t)(r + 1) * HF] = acc1;
    }
    __syncthreads();

    // Phase 2: thread t -> row = t>>3, h = (t>>1)&3, vec = t&1
    {
        const int row = t >> 3, h = (t >> 1) & 3, vec = t & 1;
        const float4* hp = (const float4*)(hs + row * HS_STRIDE + h * HID);
        const float4* ap = (const float4*)(av + vec * HF + h * HID);
        float s = 0.f;
#pragma unroll
        for (int j = 0; j < 16; j++) {
            float4 hv = hp[j], aw = ap[j];
            s += hv.x * aw.x + hv.y * aw.y + hv.z * aw.z + hv.w * aw.w;
        }
        int idx = (b * NN + row0 + row) * NH + h;
        if (vec == 0) g_E1s[idx] = s; else g_E1d[idx] = s;
    }
}

// ---------------------------------------------------------------------------
// Kernel B: 512 threads/CTA, 2 CTAs/SM. Thread owns column c=t&255 and a
// 16-dst half (half=t>>8): 8 u64 accumulators. Double-buffered weights,
// depth-4 LDG pipeline. Then +b1, ELU, proj2, e2. Grid (32, 16).
// ---------------------------------------------------------------------------
#define H2S_STRIDE 72
#define KBT 512

__global__ void __launch_bounds__(KBT, 2) kB(const int*   __restrict__ adj,
                                             const float* __restrict__ b1,
                                             const float* __restrict__ W2,
                                             const float* __restrict__ a2s,
                                             const float* __restrict__ a2d) {
    // Phase-1 layout inside big[11392] (44.5 KB):
    //   es   [2048]  @0       e1_src[s][h]
    //   ws   [8192]  @2048    double-buffered weight blocks [2][sl(32)][h(4)][d(32)]
    //   maskw[512]u  @10240
    //   ed   [128]   @10752
    //   zp   [512]   @10880
    // Phase-2 overlays:
    //   tile [8192]  @0       elu(agg)+b1, [d(32)][c(256)]
    //   h2s  [32*72] @8192
    __shared__ __align__(16) float big[11392];
    __shared__ float Zs[128];
    float*    es    = big;
    float*    ws    = big + 2048;
    unsigned* maskw = (unsigned*)(big + 10240);
    float*    ed    = big + 10752;
    float*    zp    = big + 10880;
    float*    tile  = big;
    float*    h2s   = big + 8192;

    const int b = blockIdx.x, d0 = blockIdx.y * 32;
    const int t = threadIdx.x, lane = t & 31, warp = t >> 5;

    for (int i = t; i < NN * NH; i += KBT) es[i] = g_E1s[b * NN * NH + i];
    if (t < 128) ed[t] = g_E1d[(b * NN + d0) * NH + t];

    const int* ap = adj + (size_t)b * NN * NN + d0;
    for (int s = warp; s < NN; s += 16) {
        int a = ap[s * NN + lane];
        unsigned mw = __ballot_sync(0xffffffffu, (a != 0) || (s == d0 + lane));
        if (lane == 0) maskw[s] = mw;
    }
    __syncthreads();

    u64 accp[8];
#pragma unroll
    for (int i = 0; i < 8; i++) accp[i] = pack2(0.f, 0.f);
    float zpart = 0.f;

    // fill-mapping: fdd = t&31, fhh = (t>>5)&3, slb = t>>7 (0..3); 8 sl each
    const int   fhh  = (t >> 5) & 3, fdd = t & 31;
    const float fedv = ed[fdd * NH + fhh];
    const int   slb  = t >> 7;

    // aggregation mapping
    const int c    = t & 255;
    const int half = t >> 8;        // 0: dst 0-15, 1: dst 16-31
    const int h    = c >> 6;        // head of this column

    const float* H1b = g_H1 + ((size_t)(b * NN)) * HF + c;

#define FILL_WS(blk)                                                          \
    {                                                                         \
        float* wb = ws + (((blk) & 1) << 12);                                 \
        _Pragma("unroll")                                                     \
        for (int i = 0; i < 8; i++) {                                         \
            int sl = slb + 4 * i;                                             \
            int s  = (blk) * 32 + sl;                                         \
            float sc = fedv + es[s * NH + fhh];                               \
            sc = sc >= 0.f ? sc : 0.2f * sc;                                  \
            float wv = ((maskw[s] >> fdd) & 1u) ? __expf(sc) : 0.f;           \
            wb[(sl * NH + fhh) * 32 + fdd] = wv;                              \
            zpart += wv;                                                      \
        }                                                                     \
    }

    FILL_WS(0);
    __syncthreads();

    float hv[4];
#pragma unroll
    for (int q = 0; q < 4; q++) hv[q] = H1b[(size_t)q * HF];

    for (int blk = 0; blk < 16; blk++) {
        if (blk < 15) FILL_WS(blk + 1);

        const float* wbase = ws + ((blk & 1) << 12) + half * 16;
#pragma unroll
        for (int sub = 0; sub < 8; sub++) {
            // prefetch the NEXT 4 rows while computing the current 4
            float hn[4];
            int nbase = blk * 32 + sub * 4 + 4;
            if (nbase < NN) {
#pragma unroll
                for (int q = 0; q < 4; q++)
                    hn[q] = H1b[(size_t)(nbase + q) * HF];
            }
#pragma unroll
            for (int q = 0; q < 4; q++) {
                u64 hh = pack2(hv[q], hv[q]);
                const ulonglong2* wp =
                    (const ulonglong2*)(wbase + ((sub * 4 + q) * NH + h) * 32);
#pragma unroll
                for (int j = 0; j < 4; j++) {
                    ulonglong2 w2 = wp[j];
                    ffma2(accp[2 * j],     w2.x, hh);
                    ffma2(accp[2 * j + 1], w2.y, hh);
                }
            }
#pragma unroll
            for (int q = 0; q < 4; q++) hv[q] = hn[q];
        }
        __syncthreads();
    }

    // reduce Z[d][h] over the 4 slb groups; store reciprocal
    zp[t] = zpart;
    __syncthreads();
    if (t < 128)
        Zs[(t & 31) * NH + (t >> 5)] =
            1.0f / (zp[t] + zp[t + 128] + zp[t + 256] + zp[t + 384]);
    __syncthreads();

    // normalize + b1 + ELU -> tile
    const float bv = b1[c];
#pragma unroll
    for (int p = 0; p < 8; p++) {
        float2 v = unpack2(accp[p]);
        int d = half * 16 + 2 * p;
        float o0 = v.x * Zs[d * NH + h] + bv;
        float o1 = v.y * Zs[(d + 1) * NH + h] + bv;
        tile[d * HF + c]       = o0 > 0.f ? o0 : expm1f(o0);
        tile[(d + 1) * HF + c] = o1 > 0.f ? o1 : expm1f(o1);
    }
    __syncthreads();

    // proj2: h2[d][o] = tile[d][:] @ W2[:, o]  (4 rows per thread, packed c)
    const int o = t & 63, grp = t >> 6;   // grp 0..7
    u64 accA[4], accB[4];
#pragma unroll
    for (int i = 0; i < 4; i++) { accA[i] = pack2(0.f, 0.f); accB[i] = pack2(0.f, 0.f); }
    for (int c2 = 0; c2 < HF; c2 += 4) {
        u64 wpA = pack2(W2[c2 * FOUT + o],       W2[(c2 + 1) * FOUT + o]);
        u64 wpB = pack2(W2[(c2 + 2) * FOUT + o], W2[(c2 + 3) * FOUT + o]);
#pragma unroll
        for (int i = 0; i < 4; i++) {
            ulonglong2 tv = *(const ulonglong2*)(tile + (grp * 4 + i) * HF + c2);
            ffma2(accA[i], tv.x, wpA);
            ffma2(accB[i], tv.y, wpB);
        }
    }
#pragma unroll
    for (int i = 0; i < 4; i++) {
        float2 va = unpack2(accA[i]), vb = unpack2(accB[i]);
        float v = (va.x + va.y) + (vb.x + vb.y);
        int d = grp * 4 + i;
        g_H2[((size_t)(b * NN + d0 + d)) * FOUT + o] = v;
        h2s[d * H2S_STRIDE + o] = v;
    }
    __syncthreads();

    // e2_src/e2_dst for the tile: thread t<64 -> (node = t>>1, vec = t&1)
    if (t < 64) {
        const int node = t >> 1, vec = t & 1;
        const float* aw = vec ? a2d : a2s;
        const float4* hp = (const float4*)(h2s + node * H2S_STRIDE);
        float s = 0.f;
#pragma unroll
        for (int j = 0; j < 16; j++) {
            float4 hvv = hp[j];
            s += hvv.x * aw[4 * j] + hvv.y * aw[4 * j + 1]
               + hvv.z * aw[4 * j + 2] + hvv.w * aw[4 * j + 3];
        }
        int idx = b * NN + d0 + node;
        if (vec == 0) g_E2s[idx] = s; else g_E2d[idx] = s;
    }
#undef FILL_WS
}

// ---------------------------------------------------------------------------
// Kernel C: layer-2 attention aggregation + b2 -> out. Grid (32, 16).
// Double-buffered weights + depth-8 LDG pipelining. 3 CTAs/SM.
// ---------------------------------------------------------------------------
__global__ void __launch_bounds__(256, 3) kC(const int*   __restrict__ adj,
                                             const float* __restrict__ b2,
                                             float*       __restrict__ out) {
    __shared__ float es2[NN];
    __shared__ float ed2[32];
    __shared__ unsigned maskw[NN];
    __shared__ __align__(16) float ws2[2 * 64 * 32];   // double buffer, 16 KB
    __shared__ float zp[256];
    __shared__ float Z2[32];

    const int b = blockIdx.x, d0 = blockIdx.y * 32;
    const int t = threadIdx.x, lane = t & 31, warp = t >> 5;

    for (int i = t; i < NN; i += 256) es2[i] = g_E2s[b * NN + i];
    if (t < 32) ed2[t] = g_E2d[b * NN + d0 + t];

    const int* ap = adj + (size_t)b * NN * NN + d0;
    for (int s = warp; s < NN; s += 8) {
        int a = ap[s * NN + lane];
        unsigned mw = __ballot_sync(0xffffffffu, (a != 0) || (s == d0 + lane));
        if (lane == 0) maskw[s] = mw;
    }
    __syncthreads();

    u64 accp[4];
#pragma unroll
    for (int i = 0; i < 4; i++) accp[i] = pack2(0.f, 0.f);
    float zpart = 0.f;

    const int   fdd  = t & 31, fslb = t >> 5;
    const float fedv = ed2[fdd];
    const int   o = t & 63, grp = t >> 6;
    const float* H2b = g_H2 + (size_t)b * NN * FOUT + o;

#define FILL_WS2(blk)                                                         \
    {                                                                         \
        float* wb = ws2 + (((blk) & 1) << 11);                                \
        _Pragma("unroll")                                                     \
        for (int i = 0; i < 8; i++) {                                         \
            int sl = fslb + 8 * i;                                            \
            int s  = (blk) * 64 + sl;                                         \
            float sc = fedv + es2[s];                                         \
            sc = sc >= 0.f ? sc : 0.2f * sc;                                  \
            float wv = ((maskw[s] >> fdd) & 1u) ? __expf(sc) : 0.f;           \
            wb[sl * 32 + fdd] = wv;                                           \
            zpart += wv;                                                      \
        }                                                                     \
    }

    FILL_WS2(0);
    __syncthreads();

    float hv[8];
#pragma unroll
    for (int q = 0; q < 8; q++) hv[q] = H2b[(size_t)q * FOUT];

    for (int blk = 0; blk < 8; blk++) {
        if (blk < 7) FILL_WS2(blk + 1);

        const float* wbase = ws2 + ((blk & 1) << 11);
#pragma unroll
        for (int sub = 0; sub < 8; sub++) {
            float hn[8];
            int nbase = blk * 64 + sub * 8 + 8;
            if (nbase < NN) {
#pragma unroll
                for (int q = 0; q < 8; q++)
                    hn[q] = H2b[(size_t)(nbase + q) * FOUT];
            }
#pragma unroll
            for (int q = 0; q < 8; q++) {
                u64 hh = pack2(hv[q], hv[q]);
                const ulonglong2* wp =
                    (const ulonglong2*)(wbase + (sub * 8 + q) * 32 + grp * 8);
                ulonglong2 wa = wp[0], wb2 = wp[1];
                ffma2(accp[0], wa.x, hh);
                ffma2(accp[1], wa.y, hh);
                ffma2(accp[2], wb2.x, hh);
                ffma2(accp[3], wb2.y, hh);
            }
#pragma unroll
            for (int q = 0; q < 8; q++) hv[q] = hn[q];
        }
        __syncthreads();
    }

    zp[t] = zpart;
    __syncthreads();
    if (t < 32) {
        float z = 0.f;
#pragma unroll
        for (int j = 0; j < 8; j++) z += zp[t + 32 * j];
        Z2[t] = 1.0f / z;
    }
    __syncthreads();

    const float bv = b2[o];
#pragma unroll
    for (int p = 0; p < 4; p++) {
        float2 v = unpack2(accp[p]);
        int d = grp * 8 + 2 * p;
        out[((size_t)(b * NN + d0 + d)) * FOUT + o]     = v.x * Z2[d] + bv;
        out[((size_t)(b * NN + d0 + d + 1)) * FOUT + o] = v.y * Z2[d + 1] + bv;
    }
#undef FILL_WS2
}

// ---------------------------------------------------------------------------
extern "C" void kernel_launch(void* const* d_in, const int* in_sizes, int n_in,
                              void* d_out, int out_size) {
    const float* x   = (const float*)d_in[0];
    const int*   adj = (const int*)  d_in[1];
    const float* W1  = (const float*)d_in[2];
    const float* a1s = (const float*)d_in[3];
    const float* a1d = (const float*)d_in[4];
    const float* b1  = (const float*)d_in[5];
    const float* W2  = (const float*)d_in[6];
    const float* a2s = (const float*)d_in[7];
    const float* a2d = (const float*)d_in[8];
    const float* b2  = (const float*)d_in[9];
    float* out = (float*)d_out;

    kA<<<dim3(NB, 16), 256>>>(x, W1, a1s, a1d);
    kB<<<dim3(NB, 16), KBT>>>(adj, b1, W2, a2s, a2d);
    kC<<<dim3(NB, 16), 256>>>(adj, b2, out);
}

// round 9
// speedup vs baseline: 1.3544x; 1.3544x over previous
#include <cuda_runtime.h>
#include <cuda_bf16.h>
#include <cstdint>

// Problem constants
#define NB   32
#define NN   512
#define FIN  64
#define NH   4
#define HID  64
#define HF   256   // NH*HID
#define FOUT 64

typedef unsigned long long u64;
typedef unsigned int       u32;

// ---------------- scratch (static device arrays; no allocation) -------------
__device__ __nv_bfloat16 g_B1hi[NB * NH * NN * HID];   // H1 split, [b,h,s,f]
__device__ __nv_bfloat16 g_B1lo[NB * NH * NN * HID];
__device__ __nv_bfloat16 g_B2hi[NB * NN * FOUT];       // H2 split, [b,s,f]
__device__ __nv_bfloat16 g_B2lo[NB * NN * FOUT];
__device__ float g_T1[NB * NN * HF];                   // elu(agg1)+b1, fp32
__device__ u32   g_mask[NB * 4 * NN * 4];              // [b,tile128,s,word4]
__device__ float g_E1s[NB * NH * NN], g_E1d[NB * NH * NN];   // [b,h,s]
__device__ float g_E2s[NB * NN],      g_E2d[NB * NN];

// ---------------- packed f32x2 helpers ---------------------------------------
__device__ __forceinline__ void ffma2(u64& d, u64 a, u64 b) {
    asm("fma.rn.f32x2 %0, %1, %2, %0;" : "+l"(d) : "l"(a), "l"(b));
}
__device__ __forceinline__ u64 pack2(float x, float y) {
    u64 r; asm("mov.b64 %0, {%1, %2};" : "=l"(r) : "f"(x), "f"(y)); return r;
}
__device__ __forceinline__ float2 unpack2(u64 v) {
    float2 r; asm("mov.b64 {%0, %1}, %2;" : "=f"(r.x), "=f"(r.y) : "l"(v)); return r;
}

// ---------------- mma.sync m16n8k16 bf16 -------------------------------------
__device__ __forceinline__ void mma16816(float* c, const u32* a, u32 b0, u32 b1) {
    asm volatile(
        "mma.sync.aligned.m16n8k16.row.col.f32.bf16.bf16.f32 "
        "{%0,%1,%2,%3}, {%4,%5,%6,%7}, {%8,%9}, {%0,%1,%2,%3};"
        : "+f"(c[0]), "+f"(c[1]), "+f"(c[2]), "+f"(c[3])
        : "r"(a[0]), "r"(a[1]), "r"(a[2]), "r"(a[3]), "r"(b0), "r"(b1));
}

// smem layout for aggregation kernels (byte offsets)
#define SA     72    // alpha row stride (bf16 elems): 144B = 36 words
#define ST     72    // Ht row stride
#define AG_AH  0
#define AG_AL  18432
#define AG_HTH 36864
#define AG_HTL 46080
#define AG_ES  55296
#define AG_ED  57344
#define AG_MSK 57856
#define AG_ZP  66048
#define AG_SMEM 67072

// ---------------------------------------------------------------------------
// Kernel A: H1 = x @ W1 (emitted bf16 hi/lo per-head [b,h,s,f]) + e1 [b,h,s].
// ---------------------------------------------------------------------------
#define HS_STRIDE 264

__global__ void __launch_bounds__(256, 2) kA(const float* __restrict__ x,
                                             const float* __restrict__ W1,
                                             const float* __restrict__ a1s,
                                             const float* __restrict__ a1d) {
    __shared__ __align__(16) float xs[32 * FIN];
    __shared__ __align__(16) float hs[32 * HS_STRIDE];
    __shared__ __align__(16) float av[2 * HF];

    const int b = blockIdx.x, row0 = blockIdx.y * 32;
    const int t = threadIdx.x;

    const float* xp = x + ((size_t)(b * NN + row0)) * FIN;
    for (int i = t; i < 32 * FIN; i += 256) xs[i] = xp[i];
    av[t]      = a1s[t];
    av[t + HF] = a1d[t];

    u64 w1p[32];
#pragma unroll
    for (int kk = 0; kk < 32; kk++)
        w1p[kk] = pack2(W1[(2 * kk) * HF + t], W1[(2 * kk + 1) * HF + t]);
    __syncthreads();

    const int hh = t >> 6, f = t & 63;
    __nv_bfloat16* phi = g_B1hi + ((size_t)(b * NH + hh) * NN + row0) * HID + f;
    __nv_bfloat16* plo = g_B1lo + ((size_t)(b * NH + hh) * NN + row0) * HID + f;
    const u64 z2 = pack2(0.f, 0.f);
    for (int r = 0; r < 32; r += 2) {
        const ulonglong2* xr0 = (const ulonglong2*)(xs + r * FIN);
        const ulonglong2* xr1 = (const ulonglong2*)(xs + (r + 1) * FIN);
        u64 aA0 = z2, aB0 = z2, aA1 = z2, aB1 = z2;
#pragma unroll
        for (int q = 0; q < 16; q++) {
            ulonglong2 x0 = xr0[q], x1 = xr1[q];
            ffma2(aA0, x0.x, w1p[2 * q]);
            ffma2(aB0, x0.y, w1p[2 * q + 1]);
            ffma2(aA1, x1.x, w1p[2 * q]);
            ffma2(aB1, x1.y, w1p[2 * q + 1]);
        }
        float2 fa0 = unpack2(aA0), fb0 = unpack2(aB0);
        float2 fa1 = unpack2(aA1), fb1 = unpack2(aB1);
        float acc0 = (fa0.x + fa0.y) + (fb0.x + fb0.y);
        float acc1 = (fa1.x + fa1.y) + (fb1.x + fb1.y);
        hs[r * HS_STRIDE + t]       = acc0;
        hs[(r + 1) * HS_STRIDE + t] = acc1;
        __nv_bfloat16 h0 = __float2bfloat16(acc0);
        __nv_bfloat16 h1 = __float2bfloat16(acc1);
        phi[(size_t)r * HID]       = h0;
        phi[(size_t)(r + 1) * HID] = h1;
        plo[(size_t)r * HID]       = __float2bfloat16(acc0 - __bfloat162float(h0));
        plo[(size_t)(r + 1) * HID] = __float2bfloat16(acc1 - __bfloat162float(h1));
    }
    __syncthreads();

    {   // e1: thread t -> row = t>>3, h = (t>>1)&3, vec = t&1
        const int row = t >> 3, h = (t >> 1) & 3, vec = t & 1;
        const float4* hp = (const float4*)(hs + row * HS_STRIDE + h * HID);
        const float4* ap = (const float4*)(av + vec * HF + h * HID);
        float s = 0.f;
#pragma unroll
        for (int j = 0; j < 16; j++) {
            float4 hv = hp[j], aw = ap[j];
            s += hv.x * aw.x + hv.y * aw.y + hv.z * aw.z + hv.w * aw.w;
        }
        int idx = (b * NH + h) * NN + row0 + row;
        if (vec == 0) g_E1s[idx] = s; else g_E1d[idx] = s;
    }
}

// ---------------------------------------------------------------------------
// Kernel M: bit-pack adjacency masks. mask[d][s] = adj[s][d]!=0 || d==s.
// ---------------------------------------------------------------------------
__global__ void __launch_bounds__(256) kM(const int* __restrict__ adj) {
    const int b = blockIdx.x, tile = blockIdx.y, d0 = tile * 128;
    const int t = threadIdx.x, lane = t & 31, warp = t >> 5;
    const int* ab = adj + (size_t)b * NN * NN;
    for (int s = warp; s < NN; s += 8) {
#pragma unroll
        for (int w = 0; w < 4; w++) {
            int d = d0 + w * 32 + lane;
            int a = ab[s * NN + d];
            unsigned m = __ballot_sync(0xffffffffu, (a != 0) || (s == d));
            if (lane == 0) g_mask[(((b * 4 + tile) * NN) + s) * 4 + w] = m;
        }
    }
}

// ---------------------------------------------------------------------------
// kAgg1: layer-1 masked-softmax aggregation via mma.sync (bf16 hi/lo split).
// Grid (32, 4 tiles, 4 heads). 256 thr, 3 CTAs/SM. Epilogue -> g_T1 fp32.
// ---------------------------------------------------------------------------
__global__ void __launch_bounds__(256, 3) kAgg1(const float* __restrict__ b1) {
    extern __shared__ __align__(16) char sm[];
    float* esS  = (float*)(sm + AG_ES);
    float* edS  = (float*)(sm + AG_ED);
    u32*   mskS = (u32*)  (sm + AG_MSK);
    float* zpS  = (float*)(sm + AG_ZP);

    const int b = blockIdx.x, tile = blockIdx.y, head = blockIdx.z;
    const int d0 = tile * 128;
    const int t = threadIdx.x, lane = t & 31, warp = t >> 5;

    for (int i = t; i < NN; i += 256) esS[i] = g_E1s[(b * NH + head) * NN + i];
    if (t < 128) edS[t] = g_E1d[(b * NH + head) * NN + d0 + t];
    for (int i = t; i < NN * 4; i += 256)
        mskS[i] = g_mask[((b * 4 + tile) * NN) * 4 + i];
    __syncthreads();

    // fill mapping
    const int dF = t >> 1, half = t & 1;
    const float edv = edS[dF];
    const u32 mybit = 1u << (dF & 31);
    const int mw = dF >> 5;
    u32* ahF = (u32*)(sm + AG_AH + dF * (SA * 2) + half * 64);
    u32* alF = (u32*)(sm + AG_AL + dF * (SA * 2) + half * 64);

    // Ht copy mapping
    const int sH = t >> 2, fg = t & 3;

    // mma mapping
    const int g = lane >> 2, tig = lane & 3;
    const char* Abase_h = sm + AG_AH + (warp * 16 + g) * (SA * 2) + tig * 4;
    const char* Abase_l = sm + AG_AL + (warp * 16 + g) * (SA * 2) + tig * 4;

    float acc[32];
#pragma unroll
    for (int i = 0; i < 32; i++) acc[i] = 0.f;
    float z = 0.f;

    for (int ck = 0; ck < 8; ck++) {
        const int s0 = ck * 64;
        // ---- alpha fill (trunc-split bf16 hi/lo) ----
#pragma unroll
        for (int i = 0; i < 16; i++) {
            int s = s0 + half * 32 + 2 * i;
            float sc0 = edv + esS[s];
            float sc1 = edv + esS[s + 1];
            sc0 = fmaxf(sc0, 0.2f * sc0);
            sc1 = fmaxf(sc1, 0.2f * sc1);
            float w0 = (mskS[s * 4 + mw] & mybit) ? __expf(sc0) : 0.f;
            float w1 = (mskS[(s + 1) * 4 + mw] & mybit) ? __expf(sc1) : 0.f;
            z += w0 + w1;
            u32 f0 = __float_as_uint(w0), f1 = __float_as_uint(w1);
            float h0 = __uint_as_float(f0 & 0xFFFF0000u);
            float h1 = __uint_as_float(f1 & 0xFFFF0000u);
            ahF[i] = __byte_perm(f0, f1, 0x7632);
            alF[i] = __byte_perm(__float_as_uint(w0 - h0),
                                 __float_as_uint(w1 - h1), 0x7632);
        }
        // ---- Ht copy (transpose to [f][s], stride ST) ----
        {
            const __nv_bfloat16* srch =
                g_B1hi + ((size_t)(b * NH + head) * NN + s0 + sH) * HID + fg * 16;
            const __nv_bfloat16* srcl =
                g_B1lo + ((size_t)(b * NH + head) * NN + s0 + sH) * HID + fg * 16;
            uint4 vh[2], vl[2];                         // contiguous 16-elem strips
            vh[0] = ((const uint4*)srch)[0]; vh[1] = ((const uint4*)srch)[1];
            vl[0] = ((const uint4*)srcl)[0]; vl[1] = ((const uint4*)srcl)[1];
            const __nv_bfloat16* eh = (const __nv_bfloat16*)vh;
            const __nv_bfloat16* el = (const __nv_bfloat16*)vl;
            __nv_bfloat16* Hth = (__nv_bfloat16*)(sm + AG_HTH);
            __nv_bfloat16* Htl = (__nv_bfloat16*)(sm + AG_HTL);
#pragma unroll
            for (int j = 0; j < 16; j++) {
                int f = fg * 16 + j;
                Hth[f * ST + sH] = eh[j];
                Htl[f * ST + sH] = el[j];
            }
        }
        __syncthreads();

        // ---- mma: 4 ksteps x 8 n-tiles x 3 terms ----
#pragma unroll
        for (int ks = 0; ks < 4; ks++) {
            u32 ah[4], al[4];
            ah[0] = *(const u32*)(Abase_h + ks * 32);
            ah[1] = *(const u32*)(Abase_h + 8 * SA * 2 + ks * 32);
            ah[2] = *(const u32*)(Abase_h + ks * 32 + 16);
            ah[3] = *(const u32*)(Abase_h + 8 * SA * 2 + ks * 32 + 16);
            al[0] = *(const u32*)(Abase_l + ks * 32);
            al[1] = *(const u32*)(Abase_l + 8 * SA * 2 + ks * 32);
            al[2] = *(const u32*)(Abase_l + ks * 32 + 16);
            al[3] = *(const u32*)(Abase_l + 8 * SA * 2 + ks * 32 + 16);
#pragma unroll
            for (int nt = 0; nt < 8; nt++) {
                const char* Bh = sm + AG_HTH + (nt * 8 + g) * (ST * 2) + ks * 32 + tig * 4;
                const char* Bl = sm + AG_HTL + (nt * 8 + g) * (ST * 2) + ks * 32 + tig * 4;
                u32 bh0 = *(const u32*)Bh, bh1 = *(const u32*)(Bh + 16);
                u32 bl0 = *(const u32*)Bl, bl1 = *(const u32*)(Bl + 16);
                mma16816(acc + nt * 4, ah, bh0, bh1);
                mma16816(acc + nt * 4, ah, bl0, bl1);
                mma16816(acc + nt * 4, al, bh0, bh1);
            }
        }
        __syncthreads();
    }

    // ---- epilogue: Z, normalize, +b1, ELU -> g_T1 ----
    zpS[t] = z;
    __syncthreads();
    const int r0 = warp * 16 + g, r1 = r0 + 8;
    const float rZ0 = 1.0f / (zpS[2 * r0] + zpS[2 * r0 + 1]);
    const float rZ1 = 1.0f / (zpS[2 * r1] + zpS[2 * r1 + 1]);
    float* o0 = g_T1 + ((size_t)(b * NN + d0 + r0)) * HF + head * 64;
    float* o1 = g_T1 + ((size_t)(b * NN + d0 + r1)) * HF + head * 64;
#pragma unroll
    for (int nt = 0; nt < 8; nt++) {
        int cb = nt * 8 + 2 * tig;
        float2 bv = *(const float2*)(b1 + head * 64 + cb);
        float v0 = acc[nt * 4 + 0] * rZ0 + bv.x;
        float v1 = acc[nt * 4 + 1] * rZ0 + bv.y;
        float v2 = acc[nt * 4 + 2] * rZ1 + bv.x;
        float v3 = acc[nt * 4 + 3] * rZ1 + bv.y;
        v0 = v0 > 0.f ? v0 : (__expf(v0) - 1.f);
        v1 = v1 > 0.f ? v1 : (__expf(v1) - 1.f);
        v2 = v2 > 0.f ? v2 : (__expf(v2) - 1.f);
        v3 = v3 > 0.f ? v3 : (__expf(v3) - 1.f);
        *(float2*)(o0 + cb) = make_float2(v0, v1);
        *(float2*)(o1 + cb) = make_float2(v2, v3);
    }
}

// ---------------------------------------------------------------------------
// kP: proj2 (fp32 packed FMA) + e2 + bf16 hi/lo H2. Grid (32, 16).
// ---------------------------------------------------------------------------
#define H2S_STRIDE 72

__global__ void __launch_bounds__(256) kP(const float* __restrict__ W2,
                                          const float* __restrict__ a2s,
                                          const float* __restrict__ a2d) {
    __shared__ __align__(16) float tile[32 * HF];
    __shared__ __align__(16) float h2s[32 * H2S_STRIDE];
    const int b = blockIdx.x, n0 = blockIdx.y * 32;
    const int t = threadIdx.x;

    const float4* src = (const float4*)(g_T1 + ((size_t)(b * NN + n0)) * HF);
    float4* dst4 = (float4*)tile;
    for (int i = t; i < 32 * HF / 4; i += 256) dst4[i] = src[i];
    __syncthreads();

    const int o = t & 63, grp = t >> 6;
    u64 accA[8], accB[8];
#pragma unroll
    for (int i = 0; i < 8; i++) { accA[i] = pack2(0.f, 0.f); accB[i] = pack2(0.f, 0.f); }
    for (int c = 0; c < HF; c += 4) {
        u64 wpA = pack2(W2[c * FOUT + o],       W2[(c + 1) * FOUT + o]);
        u64 wpB = pack2(W2[(c + 2) * FOUT + o], W2[(c + 3) * FOUT + o]);
#pragma unroll
        for (int i = 0; i < 8; i++) {
            ulonglong2 tv = *(const ulonglong2*)(tile + (grp * 8 + i) * HF + c);
            ffma2(accA[i], tv.x, wpA);
            ffma2(accB[i], tv.y, wpB);
        }
    }
#pragma unroll
    for (int i = 0; i < 8; i++) {
        float2 va = unpack2(accA[i]), vb = unpack2(accB[i]);
        float v = (va.x + va.y) + (vb.x + vb.y);
        int d = grp * 8 + i;
        size_t gi = ((size_t)(b * NN + n0 + d)) * FOUT + o;
        __nv_bfloat16 hi = __float2bfloat16(v);
        g_B2hi[gi] = hi;
        g_B2lo[gi] = __float2bfloat16(v - __bfloat162float(hi));
        h2s[d * H2S_STRIDE + o] = v;
    }
    __syncthreads();

    if (t < 64) {
        const int node = t >> 1, vec = t & 1;
        const float* aw = vec ? a2d : a2s;
        const float4* hp = (const float4*)(h2s + node * H2S_STRIDE);
        float s = 0.f;
#pragma unroll
        for (int j = 0; j < 16; j++) {
            float4 hv = hp[j];
            s += hv.x * aw[4 * j] + hv.y * aw[4 * j + 1]
               + hv.z * aw[4 * j + 2] + hv.w * aw[4 * j + 3];
        }
        int idx = b * NN + n0 + node;
        if (vec == 0) g_E2s[idx] = s; else g_E2d[idx] = s;
    }
}

// ---------------------------------------------------------------------------
// kAgg2: layer-2 aggregation via mma.sync + b2 -> out. Grid (32, 4).
// ---------------------------------------------------------------------------
__global__ void __launch_bounds__(256, 3) kAgg2(const float* __restrict__ b2,
                                                float* __restrict__ out) {
    extern __shared__ __align__(16) char sm[];
    float* esS  = (float*)(sm + AG_ES);
    float* edS  = (float*)(sm + AG_ED);
    u32*   mskS = (u32*)  (sm + AG_MSK);
    float* zpS  = (float*)(sm + AG_ZP);

    const int b = blockIdx.x, tile = blockIdx.y;
    const int d0 = tile * 128;
    const int t = threadIdx.x, lane = t & 31, warp = t >> 5;

    for (int i = t; i < NN; i += 256) esS[i] = g_E2s[b * NN + i];
    if (t < 128) edS[t] = g_E2d[b * NN + d0 + t];
    for (int i = t; i < NN * 4; i += 256)
        mskS[i] = g_mask[((b * 4 + tile) * NN) * 4 + i];
    __syncthreads();

    const int dF = t >> 1, half = t & 1;
    const float edv = edS[dF];
    const u32 mybit = 1u << (dF & 31);
    const int mw = dF >> 5;
    u32* ahF = (u32*)(sm + AG_AH + dF * (SA * 2) + half * 64);
    u32* alF = (u32*)(sm + AG_AL + dF * (SA * 2) + half * 64);

    const int sH = t >> 2, fg = t & 3;
    const int g = lane >> 2, tig = lane & 3;
    const char* Abase_h = sm + AG_AH + (warp * 16 + g) * (SA * 2) + tig * 4;
    const char* Abase_l = sm + AG_AL + (warp * 16 + g) * (SA * 2) + tig * 4;

    float acc[32];
#pragma unroll
    for (int i = 0; i < 32; i++) acc[i] = 0.f;
    float z = 0.f;

    for (int ck = 0; ck < 8; ck++) {
        const int s0 = ck * 64;
#pragma unroll
        for (int i = 0; i < 16; i++) {
            int s = s0 + half * 32 + 2 * i;
            float sc0 = edv + esS[s];
            float sc1 = edv + esS[s + 1];
            sc0 = fmaxf(sc0, 0.2f * sc0);
            sc1 = fmaxf(sc1, 0.2f * sc1);
            float w0 = (mskS[s * 4 + mw] & mybit) ? __expf(sc0) : 0.f;
            float w1 = (mskS[(s + 1) * 4 + mw] & mybit) ? __expf(sc1) : 0.f;
            z += w0 + w1;
            u32 f0 = __float_as_uint(w0), f1 = __float_as_uint(w1);
            float h0 = __uint_as_float(f0 & 0xFFFF0000u);
            float h1 = __uint_as_float(f1 & 0xFFFF0000u);
            ahF[i] = __byte_perm(f0, f1, 0x7632);
            alF[i] = __byte_perm(__float_as_uint(w0 - h0),
                                 __float_as_uint(w1 - h1), 0x7632);
        }
        {
            const __nv_bfloat16* srch =
                g_B2hi + ((size_t)(b * NN + s0 + sH)) * FOUT + fg * 16;
            const __nv_bfloat16* srcl =
                g_B2lo + ((size_t)(b * NN + s0 + sH)) * FOUT + fg * 16;
            uint4 vh[2], vl[2];                         // contiguous 16-elem strips
            vh[0] = ((const uint4*)srch)[0]; vh[1] = ((const uint4*)srch)[1];
            vl[0] = ((const uint4*)srcl)[0]; vl[1] = ((const uint4*)srcl)[1];
            const __nv_bfloat16* eh = (const __nv_bfloat16*)vh;
            const __nv_bfloat16* el = (const __nv_bfloat16*)vl;
            __nv_bfloat16* Hth = (__nv_bfloat16*)(sm + AG_HTH);
            __nv_bfloat16* Htl = (__nv_bfloat16*)(sm + AG_HTL);
#pragma unroll
            for (int j = 0; j < 16; j++) {
                int f = fg * 16 + j;
                Hth[f * ST + sH] = eh[j];
                Htl[f * ST + sH] = el[j];
            }
        }
        __syncthreads();

#pragma unroll
        for (int ks = 0; ks < 4; ks++) {
            u32 ah[4], al[4];
            ah[0] = *(const u32*)(Abase_h + ks * 32);
            ah[1] = *(const u32*)(Abase_h + 8 * SA * 2 + ks * 32);
            ah[2] = *(const u32*)(Abase_h + ks * 32 + 16);
            ah[3] = *(const u32*)(Abase_h + 8 * SA * 2 + ks * 32 + 16);
            al[0] = *(const u32*)(Abase_l + ks * 32);
            al[1] = *(const u32*)(Abase_l + 8 * SA * 2 + ks * 32);
            al[2] = *(const u32*)(Abase_l + ks * 32 + 16);
            al[3] = *(const u32*)(Abase_l + 8 * SA * 2 + ks * 32 + 16);
#pragma unroll
            for (int nt = 0; nt < 8; nt++) {
                const char* Bh = sm + AG_HTH + (nt * 8 + g) * (ST * 2) + ks * 32 + tig * 4;
                const char* Bl = sm + AG_HTL + (nt * 8 + g) * (ST * 2) + ks * 32 + tig * 4;
                u32 bh0 = *(const u32*)Bh, bh1 = *(const u32*)(Bh + 16);
                u32 bl0 = *(const u32*)Bl, bl1 = *(const u32*)(Bl + 16);
                mma16816(acc + nt * 4, ah, bh0, bh1);
                mma16816(acc + nt * 4, ah, bl0, bl1);
                mma16816(acc + nt * 4, al, bh0, bh1);
            }
        }
        __syncthreads();
    }

    zpS[t] = z;
    __syncthreads();
    const int r0 = warp * 16 + g, r1 = r0 + 8;
    const float rZ0 = 1.0f / (zpS[2 * r0] + zpS[2 * r0 + 1]);
    const float rZ1 = 1.0f / (zpS[2 * r1] + zpS[2 * r1 + 1]);
    float* o0 = out + ((size_t)(b * NN + d0 + r0)) * FOUT;
    float* o1 = out + ((size_t)(b * NN + d0 + r1)) * FOUT;
#pragma unroll
    for (int nt = 0; nt < 8; nt++) {
        int cb = nt * 8 + 2 * tig;
        float2 bv = *(const float2*)(b2 + cb);
        *(float2*)(o0 + cb) = make_float2(acc[nt * 4 + 0] * rZ0 + bv.x,
                                          acc[nt * 4 + 1] * rZ0 + bv.y);
        *(float2*)(o1 + cb) = make_float2(acc[nt * 4 + 2] * rZ1 + bv.x,
                                          acc[nt * 4 + 3] * rZ1 + bv.y);
    }
}

// ---------------------------------------------------------------------------
extern "C" void kernel_launch(void* const* d_in, const int* in_sizes, int n_in,
                              void* d_out, int out_size) {
    const float* x   = (const float*)d_in[0];
    const int*   adj = (const int*)  d_in[1];
    const float* W1  = (const float*)d_in[2];
    const float* a1s = (const float*)d_in[3];
    const float* a1d = (const float*)d_in[4];
    const float* b1  = (const float*)d_in[5];
    const float* W2  = (const float*)d_in[6];
    const float* a2s = (const float*)d_in[7];
    const float* a2d = (const float*)d_in[8];
    const float* b2  = (const float*)d_in[9];
    float* out = (float*)d_out;

    cudaFuncSetAttribute(kAgg1, cudaFuncAttributeMaxDynamicSharedMemorySize, AG_SMEM);
    cudaFuncSetAttribute(kAgg2, cudaFuncAttributeMaxDynamicSharedMemorySize, AG_SMEM);

    kA   <<<dim3(NB, 16), 256>>>(x, W1, a1s, a1d);
    kM   <<<dim3(NB, 4),  256>>>(adj);
    kAgg1<<<dim3(NB, 4, NH), 256, AG_SMEM>>>(b1);
    kP   <<<dim3(NB, 16), 256>>>(W2, a2s, a2d);
    kAgg2<<<dim3(NB, 4),  256, AG_SMEM>>>(b2, out);
}

// round 10
// speedup vs baseline: 1.4174x; 1.0465x over previous
#include <cuda_runtime.h>
#include <cuda_bf16.h>
#include <cstdint>

// Problem constants
#define NB   32
#define NN   512
#define FIN  64
#define NH   4
#define HID  64
#define HF   256   // NH*HID
#define FOUT 64

typedef unsigned long long u64;
typedef unsigned int       u32;

// ---------------- scratch (static device arrays; no allocation) -------------
__device__ __nv_bfloat16 g_B1hi[NB * NH * NN * HID];   // H1 split, [b,h,s,f]
__device__ __nv_bfloat16 g_B1lo[NB * NH * NN * HID];
__device__ __nv_bfloat16 g_B2hi[NB * NN * FOUT];       // H2 split, [b,s,f]
__device__ __nv_bfloat16 g_B2lo[NB * NN * FOUT];
__device__ float g_T1[NB * NN * HF];                   // elu(agg1)+b1, fp32
__device__ u32   g_mask[NB * 4 * NN * 4];              // [b,tile128,s,word4]
__device__ float g_E1s[NB * NH * NN], g_E1d[NB * NH * NN];   // [b,h,s]
__device__ float g_E2s[NB * NN],      g_E2d[NB * NN];

// ---------------- packed f32x2 helpers ---------------------------------------
__device__ __forceinline__ void ffma2(u64& d, u64 a, u64 b) {
    asm("fma.rn.f32x2 %0, %1, %2, %0;" : "+l"(d) : "l"(a), "l"(b));
}
__device__ __forceinline__ u64 pack2(float x, float y) {
    u64 r; asm("mov.b64 %0, {%1, %2};" : "=l"(r) : "f"(x), "f"(y)); return r;
}
__device__ __forceinline__ float2 unpack2(u64 v) {
    float2 r; asm("mov.b64 {%0, %1}, %2;" : "=f"(r.x), "=f"(r.y) : "l"(v)); return r;
}

// ---------------- mma.sync m16n8k16 bf16 -------------------------------------
__device__ __forceinline__ void mma16816(float* c, const u32* a, u32 b0, u32 b1) {
    asm volatile(
        "mma.sync.aligned.m16n8k16.row.col.f32.bf16.bf16.f32 "
        "{%0,%1,%2,%3}, {%4,%5,%6,%7}, {%8,%9}, {%0,%1,%2,%3};"
        : "+f"(c[0]), "+f"(c[1]), "+f"(c[2]), "+f"(c[3])
        : "r"(a[0]), "r"(a[1]), "r"(a[2]), "r"(a[3]), "r"(b0), "r"(b1));
}

// smem layout for aggregation kernels (byte offsets)
#define SA     72    // alpha row stride (bf16 elems): 144B = 36 words
#define ST     72    // Ht row stride
#define AG_AH  0
#define AG_AL  18432
#define AG_HTH 36864
#define AG_HTL 46080
#define AG_ES  55296
#define AG_ED  57344
#define AG_MSK 57856
#define AG_ZP  66048
#define AG_SMEM 67072

// ---------------------------------------------------------------------------
// Kernel A: H1 = x @ W1 (emitted bf16 hi/lo per-head [b,h,s,f]) + e1 [b,h,s].
// ---------------------------------------------------------------------------
#define HS_STRIDE 264

__global__ void __launch_bounds__(256, 2) kA(const float* __restrict__ x,
                                             const float* __restrict__ W1,
                                             const float* __restrict__ a1s,
                                             const float* __restrict__ a1d) {
    __shared__ __align__(16) float xs[32 * FIN];
    __shared__ __align__(16) float hs[32 * HS_STRIDE];
    __shared__ __align__(16) float av[2 * HF];

    const int b = blockIdx.x, row0 = blockIdx.y * 32;
    const int t = threadIdx.x;

    const float* xp = x + ((size_t)(b * NN + row0)) * FIN;
    for (int i = t; i < 32 * FIN; i += 256) xs[i] = xp[i];
    av[t]      = a1s[t];
    av[t + HF] = a1d[t];

    u64 w1p[32];
#pragma unroll
    for (int kk = 0; kk < 32; kk++)
        w1p[kk] = pack2(W1[(2 * kk) * HF + t], W1[(2 * kk + 1) * HF + t]);
    __syncthreads();

    const int hh = t >> 6, f = t & 63;
    __nv_bfloat16* phi = g_B1hi + ((size_t)(b * NH + hh) * NN + row0) * HID + f;
    __nv_bfloat16* plo = g_B1lo + ((size_t)(b * NH + hh) * NN + row0) * HID + f;
    const u64 z2 = pack2(0.f, 0.f);
    for (int r = 0; r < 32; r += 2) {
        const ulonglong2* xr0 = (const ulonglong2*)(xs + r * FIN);
        const ulonglong2* xr1 = (const ulonglong2*)(xs + (r + 1) * FIN);
        u64 aA0 = z2, aB0 = z2, aA1 = z2, aB1 = z2;
#pragma unroll
        for (int q = 0; q < 16; q++) {
            ulonglong2 x0 = xr0[q], x1 = xr1[q];
            ffma2(aA0, x0.x, w1p[2 * q]);
            ffma2(aB0, x0.y, w1p[2 * q + 1]);
            ffma2(aA1, x1.x, w1p[2 * q]);
            ffma2(aB1, x1.y, w1p[2 * q + 1]);
        }
        float2 fa0 = unpack2(aA0), fb0 = unpack2(aB0);
        float2 fa1 = unpack2(aA1), fb1 = unpack2(aB1);
        float acc0 = (fa0.x + fa0.y) + (fb0.x + fb0.y);
        float acc1 = (fa1.x + fa1.y) + (fb1.x + fb1.y);
        hs[r * HS_STRIDE + t]       = acc0;
        hs[(r + 1) * HS_STRIDE + t] = acc1;
        __nv_bfloat16 h0 = __float2bfloat16(acc0);
        __nv_bfloat16 h1 = __float2bfloat16(acc1);
        phi[(size_t)r * HID]       = h0;
        phi[(size_t)(r + 1) * HID] = h1;
        plo[(size_t)r * HID]       = __float2bfloat16(acc0 - __bfloat162float(h0));
        plo[(size_t)(r + 1) * HID] = __float2bfloat16(acc1 - __bfloat162float(h1));
    }
    __syncthreads();

    {   // e1: thread t -> row = t>>3, h = (t>>1)&3, vec = t&1
        const int row = t >> 3, h = (t >> 1) & 3, vec = t & 1;
        const float4* hp = (const float4*)(hs + row * HS_STRIDE + h * HID);
        const float4* ap = (const float4*)(av + vec * HF + h * HID);
        float s = 0.f;
#pragma unroll
        for (int j = 0; j < 16; j++) {
            float4 hv = hp[j], aw = ap[j];
            s += hv.x * aw.x + hv.y * aw.y + hv.z * aw.z + hv.w * aw.w;
        }
        int idx = (b * NH + h) * NN + row0 + row;
        if (vec == 0) g_E1s[idx] = s; else g_E1d[idx] = s;
    }
}

// ---------------------------------------------------------------------------
// Kernel M: bit-pack adjacency masks. mask[d][s] = adj[s][d]!=0 || d==s.
// ---------------------------------------------------------------------------
__global__ void __launch_bounds__(256) kM(const int* __restrict__ adj) {
    const int b = blockIdx.x, tile = blockIdx.y, d0 = tile * 128;
    const int t = threadIdx.x, lane = t & 31, warp = t >> 5;
    const int* ab = adj + (size_t)b * NN * NN;
    for (int s = warp; s < NN; s += 8) {
#pragma unroll
        for (int w = 0; w < 4; w++) {
            int d = d0 + w * 32 + lane;
            int a = ab[s * NN + d];
            unsigned m = __ballot_sync(0xffffffffu, (a != 0) || (s == d));
            if (lane == 0) g_mask[(((b * 4 + tile) * NN) + s) * 4 + w] = m;
        }
    }
}

// ---------------------------------------------------------------------------
// kAgg1: layer-1 masked-softmax aggregation via mma.sync (bf16 hi/lo split).
// Grid (32, 4 tiles, 4 heads). 256 thr, 3 CTAs/SM. Epilogue -> g_T1 fp32.
// ---------------------------------------------------------------------------
__global__ void __launch_bounds__(256, 3) kAgg1(const float* __restrict__ b1) {
    extern __shared__ __align__(16) char sm[];
    float* esS  = (float*)(sm + AG_ES);
    float* edS  = (float*)(sm + AG_ED);
    u32*   mskS = (u32*)  (sm + AG_MSK);
    float* zpS  = (float*)(sm + AG_ZP);

    const int b = blockIdx.x, tile = blockIdx.y, head = blockIdx.z;
    const int d0 = tile * 128;
    const int t = threadIdx.x, lane = t & 31, warp = t >> 5;

    for (int i = t; i < NN; i += 256) esS[i] = g_E1s[(b * NH + head) * NN + i];
    if (t < 128) edS[t] = g_E1d[(b * NH + head) * NN + d0 + t];
    for (int i = t; i < NN * 4; i += 256)
        mskS[i] = g_mask[((b * 4 + tile) * NN) * 4 + i];
    __syncthreads();

    // fill mapping
    const int dF = t >> 1, half = t & 1;
    const float edv = edS[dF];
    const u32 mybit = 1u << (dF & 31);
    const int mw = dF >> 5;
    u32* ahF = (u32*)(sm + AG_AH + dF * (SA * 2) + half * 64);
    u32* alF = (u32*)(sm + AG_AL + dF * (SA * 2) + half * 64);

    // Ht copy mapping
    const int sH = t >> 2, fg = t & 3;

    // mma mapping
    const int g = lane >> 2, tig = lane & 3;
    const char* Abase_h = sm + AG_AH + (warp * 16 + g) * (SA * 2) + tig * 4;
    const char* Abase_l = sm + AG_AL + (warp * 16 + g) * (SA * 2) + tig * 4;

    float acc[32];
#pragma unroll
    for (int i = 0; i < 32; i++) acc[i] = 0.f;
    float z = 0.f;

    for (int ck = 0; ck < 8; ck++) {
        const int s0 = ck * 64;
        // ---- alpha fill (trunc-split bf16 hi/lo) ----
#pragma unroll
        for (int i = 0; i < 16; i++) {
            int s = s0 + half * 32 + 2 * i;
            float sc0 = edv + esS[s];
            float sc1 = edv + esS[s + 1];
            sc0 = fmaxf(sc0, 0.2f * sc0);
            sc1 = fmaxf(sc1, 0.2f * sc1);
            float w0 = (mskS[s * 4 + mw] & mybit) ? __expf(sc0) : 0.f;
            float w1 = (mskS[(s + 1) * 4 + mw] & mybit) ? __expf(sc1) : 0.f;
            z += w0 + w1;
            u32 f0 = __float_as_uint(w0), f1 = __float_as_uint(w1);
            float h0 = __uint_as_float(f0 & 0xFFFF0000u);
            float h1 = __uint_as_float(f1 & 0xFFFF0000u);
            ahF[i] = __byte_perm(f0, f1, 0x7632);
            alF[i] = __byte_perm(__float_as_uint(w0 - h0),
                                 __float_as_uint(w1 - h1), 0x7632);
        }
        // ---- Ht copy (transpose to [f][s], stride ST) ----
        {
            const __nv_bfloat16* srch =
                g_B1hi + ((size_t)(b * NH + head) * NN + s0 + sH) * HID + fg * 16;
            const __nv_bfloat16* srcl =
                g_B1lo + ((size_t)(b * NH + head) * NN + s0 + sH) * HID + fg * 16;
            uint4 vh[2], vl[2];                         // contiguous 16-elem strips
            vh[0] = ((const uint4*)srch)[0]; vh[1] = ((const uint4*)srch)[1];
            vl[0] = ((const uint4*)srcl)[0]; vl[1] = ((const uint4*)srcl)[1];
            const __nv_bfloat16* eh = (const __nv_bfloat16*)vh;
            const __nv_bfloat16* el = (const __nv_bfloat16*)vl;
            __nv_bfloat16* Hth = (__nv_bfloat16*)(sm + AG_HTH);
            __nv_bfloat16* Htl = (__nv_bfloat16*)(sm + AG_HTL);
#pragma unroll
            for (int j = 0; j < 16; j++) {
                int f = fg * 16 + j;
                Hth[f * ST + sH] = eh[j];
                Htl[f * ST + sH] = el[j];
            }
        }
        __syncthreads();

        // ---- mma: 4 ksteps x 8 n-tiles x 3 terms ----
#pragma unroll
        for (int ks = 0; ks < 4; ks++) {
            u32 ah[4], al[4];
            ah[0] = *(const u32*)(Abase_h + ks * 32);
            ah[1] = *(const u32*)(Abase_h + 8 * SA * 2 + ks * 32);
            ah[2] = *(const u32*)(Abase_h + ks * 32 + 16);
            ah[3] = *(const u32*)(Abase_h + 8 * SA * 2 + ks * 32 + 16);
            al[0] = *(const u32*)(Abase_l + ks * 32);
            al[1] = *(const u32*)(Abase_l + 8 * SA * 2 + ks * 32);
            al[2] = *(const u32*)(Abase_l + ks * 32 + 16);
            al[3] = *(const u32*)(Abase_l + 8 * SA * 2 + ks * 32 + 16);
#pragma unroll
            for (int nt = 0; nt < 8; nt++) {
                const char* Bh = sm + AG_HTH + (nt * 8 + g) * (ST * 2) + ks * 32 + tig * 4;
                const char* Bl = sm + AG_HTL + (nt * 8 + g) * (ST * 2) + ks * 32 + tig * 4;
                u32 bh0 = *(const u32*)Bh, bh1 = *(const u32*)(Bh + 16);
                u32 bl0 = *(const u32*)Bl, bl1 = *(const u32*)(Bl + 16);
                mma16816(acc + nt * 4, ah, bh0, bh1);
                mma16816(acc + nt * 4, ah, bl0, bl1);
                mma16816(acc + nt * 4, al, bh0, bh1);
            }
        }
        __syncthreads();
    }

    // ---- epilogue: Z, normalize, +b1, ELU -> g_T1 ----
    zpS[t] = z;
    __syncthreads();
    const int r0 = warp * 16 + g, r1 = r0 + 8;
    const float rZ0 = 1.0f / (zpS[2 * r0] + zpS[2 * r0 + 1]);
    const float rZ1 = 1.0f / (zpS[2 * r1] + zpS[2 * r1 + 1]);
    float* o0 = g_T1 + ((size_t)(b * NN + d0 + r0)) * HF + head * 64;
    float* o1 = g_T1 + ((size_t)(b * NN + d0 + r1)) * HF + head * 64;
#pragma unroll
    for (int nt = 0; nt < 8; nt++) {
        int cb = nt * 8 + 2 * tig;
        float2 bv = *(const float2*)(b1 + head * 64 + cb);
        float v0 = acc[nt * 4 + 0] * rZ0 + bv.x;
        float v1 = acc[nt * 4 + 1] * rZ0 + bv.y;
        float v2 = acc[nt * 4 + 2] * rZ1 + bv.x;
        float v3 = acc[nt * 4 + 3] * rZ1 + bv.y;
        v0 = v0 > 0.f ? v0 : (__expf(v0) - 1.f);
        v1 = v1 > 0.f ? v1 : (__expf(v1) - 1.f);
        v2 = v2 > 0.f ? v2 : (__expf(v2) - 1.f);
        v3 = v3 > 0.f ? v3 : (__expf(v3) - 1.f);
        *(float2*)(o0 + cb) = make_float2(v0, v1);
        *(float2*)(o1 + cb) = make_float2(v2, v3);
    }
}

// ---------------------------------------------------------------------------
// kP: proj2 with W2 staged through smem (64-row chunks) + e2 + bf16 hi/lo H2.
// Grid (32, 16). Dynamic smem: tile 32KB | w2s 16KB | h2s 9KB.
// ---------------------------------------------------------------------------
#define H2S_STRIDE 72
#define KP_OFF_W2  32768
#define KP_OFF_H2S 49152
#define KP_SMEM    (49152 + 32 * H2S_STRIDE * 4)

__global__ void __launch_bounds__(256) kP(const float* __restrict__ W2,
                                          const float* __restrict__ a2s,
                                          const float* __restrict__ a2d) {
    extern __shared__ __align__(16) char smp[];
    float* tile = (float*)smp;
    float* w2s  = (float*)(smp + KP_OFF_W2);
    float* h2s  = (float*)(smp + KP_OFF_H2S);
    const int b = blockIdx.x, n0 = blockIdx.y * 32;
    const int t = threadIdx.x;

    const float4* src = (const float4*)(g_T1 + ((size_t)(b * NN + n0)) * HF);
    for (int i = t; i < 32 * HF / 4; i += 256) ((float4*)tile)[i] = src[i];

    const int o = t & 63, grp = t >> 6;
    u64 accA[8], accB[8];
#pragma unroll
    for (int i = 0; i < 8; i++) { accA[i] = pack2(0.f, 0.f); accB[i] = pack2(0.f, 0.f); }

    for (int cc = 0; cc < 4; cc++) {
        if (cc) __syncthreads();                 // protect w2s reuse
        const float4* wsrc = (const float4*)(W2 + cc * 64 * FOUT);
        for (int i = t; i < 64 * FOUT / 4; i += 256) ((float4*)w2s)[i] = wsrc[i];
        __syncthreads();                          // w2s (and, on cc=0, tile) ready
#pragma unroll
        for (int cl = 0; cl < 64; cl += 4) {
            const int c = cc * 64 + cl;
            u64 wpA = pack2(w2s[cl * FOUT + o],       w2s[(cl + 1) * FOUT + o]);
            u64 wpB = pack2(w2s[(cl + 2) * FOUT + o], w2s[(cl + 3) * FOUT + o]);
#pragma unroll
            for (int i = 0; i < 8; i++) {
                ulonglong2 tv = *(const ulonglong2*)(tile + (grp * 8 + i) * HF + c);
                ffma2(accA[i], tv.x, wpA);
                ffma2(accB[i], tv.y, wpB);
            }
        }
    }
#pragma unroll
    for (int i = 0; i < 8; i++) {
        float2 va = unpack2(accA[i]), vb = unpack2(accB[i]);
        float v = (va.x + va.y) + (vb.x + vb.y);
        int d = grp * 8 + i;
        size_t gi = ((size_t)(b * NN + n0 + d)) * FOUT + o;
        __nv_bfloat16 hi = __float2bfloat16(v);
        g_B2hi[gi] = hi;
        g_B2lo[gi] = __float2bfloat16(v - __bfloat162float(hi));
        h2s[d * H2S_STRIDE + o] = v;
    }
    __syncthreads();

    if (t < 64) {
        const int node = t >> 1, vec = t & 1;
        const float* aw = vec ? a2d : a2s;
        const float4* hp = (const float4*)(h2s + node * H2S_STRIDE);
        float s = 0.f;
#pragma unroll
        for (int j = 0; j < 16; j++) {
            float4 hv = hp[j];
            s += hv.x * aw[4 * j] + hv.y * aw[4 * j + 1]
               + hv.z * aw[4 * j + 2] + hv.w * aw[4 * j + 3];
        }
        int idx = b * NN + n0 + node;
        if (vec == 0) g_E2s[idx] = s; else g_E2d[idx] = s;
    }
}

// ---------------------------------------------------------------------------
// kAgg2: layer-2 aggregation via mma.sync + b2 -> out. Grid (32, 4, 2):
// z splits the 64 output columns into 32-col halves (alpha duplicated per z).
// ---------------------------------------------------------------------------
__global__ void __launch_bounds__(256, 3) kAgg2(const float* __restrict__ b2,
                                                float* __restrict__ out) {
    extern __shared__ __align__(16) char sm[];
    float* esS  = (float*)(sm + AG_ES);
    float* edS  = (float*)(sm + AG_ED);
    u32*   mskS = (u32*)  (sm + AG_MSK);
    float* zpS  = (float*)(sm + AG_ZP);

    const int b = blockIdx.x, tile = blockIdx.y, ncol0 = blockIdx.z * 32;
    const int d0 = tile * 128;
    const int t = threadIdx.x, lane = t & 31, warp = t >> 5;

    for (int i = t; i < NN; i += 256) esS[i] = g_E2s[b * NN + i];
    if (t < 128) edS[t] = g_E2d[b * NN + d0 + t];
    for (int i = t; i < NN * 4; i += 256)
        mskS[i] = g_mask[((b * 4 + tile) * NN) * 4 + i];
    __syncthreads();

    const int dF = t >> 1, half = t & 1;
    const float edv = edS[dF];
    const u32 mybit = 1u << (dF & 31);
    const int mw = dF >> 5;
    u32* ahF = (u32*)(sm + AG_AH + dF * (SA * 2) + half * 64);
    u32* alF = (u32*)(sm + AG_AL + dF * (SA * 2) + half * 64);

    const int g = lane >> 2, tig = lane & 3;
    const char* Abase_h = sm + AG_AH + (warp * 16 + g) * (SA * 2) + tig * 4;
    const char* Abase_l = sm + AG_AL + (warp * 16 + g) * (SA * 2) + tig * 4;

    float acc[16];
#pragma unroll
    for (int i = 0; i < 16; i++) acc[i] = 0.f;
    float z = 0.f;

    for (int ck = 0; ck < 8; ck++) {
        const int s0 = ck * 64;
#pragma unroll
        for (int i = 0; i < 16; i++) {
            int s = s0 + half * 32 + 2 * i;
            float sc0 = edv + esS[s];
            float sc1 = edv + esS[s + 1];
            sc0 = fmaxf(sc0, 0.2f * sc0);
            sc1 = fmaxf(sc1, 0.2f * sc1);
            float w0 = (mskS[s * 4 + mw] & mybit) ? __expf(sc0) : 0.f;
            float w1 = (mskS[(s + 1) * 4 + mw] & mybit) ? __expf(sc1) : 0.f;
            z += w0 + w1;
            u32 f0 = __float_as_uint(w0), f1 = __float_as_uint(w1);
            float h0 = __uint_as_float(f0 & 0xFFFF0000u);
            float h1 = __uint_as_float(f1 & 0xFFFF0000u);
            ahF[i] = __byte_perm(f0, f1, 0x7632);
            alF[i] = __byte_perm(__float_as_uint(w0 - h0),
                                 __float_as_uint(w1 - h1), 0x7632);
        }
        if (t < 128) {   // Ht copy: 32 cols (this z-half), 64 s rows
            const int sH2 = t >> 1, fg2 = t & 1;
            const __nv_bfloat16* srch =
                g_B2hi + ((size_t)(b * NN + s0 + sH2)) * FOUT + ncol0 + fg2 * 16;
            const __nv_bfloat16* srcl =
                g_B2lo + ((size_t)(b * NN + s0 + sH2)) * FOUT + ncol0 + fg2 * 16;
            uint4 vh[2], vl[2];
            vh[0] = ((const uint4*)srch)[0]; vh[1] = ((const uint4*)srch)[1];
            vl[0] = ((const uint4*)srcl)[0]; vl[1] = ((const uint4*)srcl)[1];
            const __nv_bfloat16* eh = (const __nv_bfloat16*)vh;
            const __nv_bfloat16* el = (const __nv_bfloat16*)vl;
            __nv_bfloat16* Hth = (__nv_bfloat16*)(sm + AG_HTH);
            __nv_bfloat16* Htl = (__nv_bfloat16*)(sm + AG_HTL);
#pragma unroll
            for (int j = 0; j < 16; j++) {
                int f = fg2 * 16 + j;
                Hth[f * ST + sH2] = eh[j];
                Htl[f * ST + sH2] = el[j];
            }
        }
        __syncthreads();

#pragma unroll
        for (int ks = 0; ks < 4; ks++) {
            u32 ah[4], al[4];
            ah[0] = *(const u32*)(Abase_h + ks * 32);
            ah[1] = *(const u32*)(Abase_h + 8 * SA * 2 + ks * 32);
            ah[2] = *(const u32*)(Abase_h + ks * 32 + 16);
            ah[3] = *(const u32*)(Abase_h + 8 * SA * 2 + ks * 32 + 16);
            al[0] = *(const u32*)(Abase_l + ks * 32);
            al[1] = *(const u32*)(Abase_l + 8 * SA * 2 + ks * 32);
            al[2] = *(const u32*)(Abase_l + ks * 32 + 16);
            al[3] = *(const u32*)(Abase_l + 8 * SA * 2 + ks * 32 + 16);
#pragma unroll
            for (int nt = 0; nt < 4; nt++) {
                const char* Bh = sm + AG_HTH + (nt * 8 + g) * (ST * 2) + ks * 32 + tig * 4;
                const char* Bl = sm + AG_HTL + (nt * 8 + g) * (ST * 2) + ks * 32 + tig * 4;
                u32 bh0 = *(const u32*)Bh, bh1 = *(const u32*)(Bh + 16);
                u32 bl0 = *(const u32*)Bl, bl1 = *(const u32*)(Bl + 16);
                mma16816(acc + nt * 4, ah, bh0, bh1);
                mma16816(acc + nt * 4, ah, bl0, bl1);
                mma16816(acc + nt * 4, al, bh0, bh1);
            }
        }
        __syncthreads();
    }

    zpS[t] = z;
    __syncthreads();
    const int r0 = warp * 16 + g, r1 = r0 + 8;
    const float rZ0 = 1.0f / (zpS[2 * r0] + zpS[2 * r0 + 1]);
    const float rZ1 = 1.0f / (zpS[2 * r1] + zpS[2 * r1 + 1]);
    float* o0 = out + ((size_t)(b * NN + d0 + r0)) * FOUT + ncol0;
    float* o1 = out + ((size_t)(b * NN + d0 + r1)) * FOUT + ncol0;
#pragma unroll
    for (int nt = 0; nt < 4; nt++) {
        int cb = nt * 8 + 2 * tig;
        float2 bv = *(const float2*)(b2 + ncol0 + cb);
        *(float2*)(o0 + cb) = make_float2(acc[nt * 4 + 0] * rZ0 + bv.x,
                                          acc[nt * 4 + 1] * rZ0 + bv.y);
        *(float2*)(o1 + cb) = make_float2(acc[nt * 4 + 2] * rZ1 + bv.x,
                                          acc[nt * 4 + 3] * rZ1 + bv.y);
    }
}

// ---------------------------------------------------------------------------
extern "C" void kernel_launch(void* const* d_in, const int* in_sizes, int n_in,
                              void* d_out, int out_size) {
    const float* x   = (const float*)d_in[0];
    const int*   adj = (const int*)  d_in[1];
    const float* W1  = (const float*)d_in[2];
    const float* a1s = (const float*)d_in[3];
    const float* a1d = (const float*)d_in[4];
    const float* b1  = (const float*)d_in[5];
    const float* W2  = (const float*)d_in[6];
    const float* a2s = (const float*)d_in[7];
    const float* a2d = (const float*)d_in[8];
    const float* b2  = (const float*)d_in[9];
    float* out = (float*)d_out;

    cudaFuncSetAttribute(kAgg1, cudaFuncAttributeMaxDynamicSharedMemorySize, AG_SMEM);
    cudaFuncSetAttribute(kAgg2, cudaFuncAttributeMaxDynamicSharedMemorySize, AG_SMEM);
    cudaFuncSetAttribute(kP,    cudaFuncAttributeMaxDynamicSharedMemorySize, KP_SMEM);

    kA   <<<dim3(NB, 16), 256>>>(x, W1, a1s, a1d);
    kM   <<<dim3(NB, 4),  256>>>(adj);
    kAgg1<<<dim3(NB, 4, NH), 256, AG_SMEM>>>(b1);
    kP   <<<dim3(NB, 16), 256, KP_SMEM>>>(W2, a2s, a2d);
    kAgg2<<<dim3(NB, 4, 2), 256, AG_SMEM>>>(b2, out);
}

// round 11
// speedup vs baseline: 1.4195x; 1.0015x over previous
#include <cuda_runtime.h>
#include <cuda_bf16.h>
#include <cstdint>

// Problem constants
#define NB   32
#define NN   512
#define FIN  64
#define NH   4
#define HID  64
#define HF   256   // NH*HID
#define FOUT 64

typedef unsigned long long u64;
typedef unsigned int       u32;

// ---------------- scratch (static device arrays; no allocation) -------------
__device__ __nv_bfloat16 g_B1hi[NB * NH * NN * HID];   // H1 split, [b,h,s,f]
__device__ __nv_bfloat16 g_B1lo[NB * NH * NN * HID];
__device__ __nv_bfloat16 g_B2hi[NB * NN * FOUT];       // H2 split, [b,s,f]
__device__ __nv_bfloat16 g_B2lo[NB * NN * FOUT];
__device__ float g_T1[NB * NN * HF];                   // elu(agg1)+b1, fp32
__device__ u32   g_mask[NB * 4 * NN * 4];              // [b,tile128,s,word4]
__device__ float g_E1s[NB * NH * NN], g_E1d[NB * NH * NN];   // [b,h,s]
__device__ float g_E2s[NB * NN],      g_E2d[NB * NN];

// ---------------- packed f32x2 helpers ---------------------------------------
__device__ __forceinline__ void ffma2(u64& d, u64 a, u64 b) {
    asm("fma.rn.f32x2 %0, %1, %2, %0;" : "+l"(d) : "l"(a), "l"(b));
}
__device__ __forceinline__ u64 pack2(float x, float y) {
    u64 r; asm("mov.b64 %0, {%1, %2};" : "=l"(r) : "f"(x), "f"(y)); return r;
}
__device__ __forceinline__ float2 unpack2(u64 v) {
    float2 r; asm("mov.b64 {%0, %1}, %2;" : "=f"(r.x), "=f"(r.y) : "l"(v)); return r;
}

// ---------------- mma.sync m16n8k16 bf16 + ldmatrix --------------------------
__device__ __forceinline__ void mma16816(float* c, const u32* a, u32 b0, u32 b1) {
    asm volatile(
        "mma.sync.aligned.m16n8k16.row.col.f32.bf16.bf16.f32 "
        "{%0,%1,%2,%3}, {%4,%5,%6,%7}, {%8,%9}, {%0,%1,%2,%3};"
        : "+f"(c[0]), "+f"(c[1]), "+f"(c[2]), "+f"(c[3])
        : "r"(a[0]), "r"(a[1]), "r"(a[2]), "r"(a[3]), "r"(b0), "r"(b1));
}
__device__ __forceinline__ void ldsm_x4(u32& r0, u32& r1, u32& r2, u32& r3, u32 addr) {
    asm volatile("ldmatrix.sync.aligned.m8n8.x4.shared.b16 {%0,%1,%2,%3}, [%4];"
                 : "=r"(r0), "=r"(r1), "=r"(r2), "=r"(r3) : "r"(addr));
}
__device__ __forceinline__ u32 smem_u32(const void* p) {
    u32 a; asm("{ .reg .u64 t; cvta.to.shared.u64 t, %1; cvt.u32.u64 %0, t; }"
               : "=r"(a) : "l"(p));
    return a;
}

// smem layout for aggregation kernels (byte offsets)
#define SA     72    // alpha row stride (bf16 elems): 144B = 36 words
#define ST     72    // Ht row stride
#define AG_AH  0
#define AG_AL  18432
#define AG_HTH 36864
#define AG_HTL 46080
#define AG_ES  55296
#define AG_ED  57344
#define AG_MSK 57856
#define AG_ZP  66048
#define AG_SMEM 67072

// ---------------------------------------------------------------------------
// Kernel A: H1 = x @ W1 (emitted bf16 hi/lo per-head [b,h,s,f]) + e1 [b,h,s].
// ---------------------------------------------------------------------------
#define HS_STRIDE 264

__global__ void __launch_bounds__(256, 2) kA(const float* __restrict__ x,
                                             const float* __restrict__ W1,
                                             const float* __restrict__ a1s,
                                             const float* __restrict__ a1d) {
    __shared__ __align__(16) float xs[32 * FIN];
    __shared__ __align__(16) float hs[32 * HS_STRIDE];
    __shared__ __align__(16) float av[2 * HF];

    const int b = blockIdx.x, row0 = blockIdx.y * 32;
    const int t = threadIdx.x;

    const float* xp = x + ((size_t)(b * NN + row0)) * FIN;
    for (int i = t; i < 32 * FIN; i += 256) xs[i] = xp[i];
    av[t]      = a1s[t];
    av[t + HF] = a1d[t];

    u64 w1p[32];
#pragma unroll
    for (int kk = 0; kk < 32; kk++)
        w1p[kk] = pack2(W1[(2 * kk) * HF + t], W1[(2 * kk + 1) * HF + t]);
    __syncthreads();

    const int hh = t >> 6, f = t & 63;
    __nv_bfloat16* phi = g_B1hi + ((size_t)(b * NH + hh) * NN + row0) * HID + f;
    __nv_bfloat16* plo = g_B1lo + ((size_t)(b * NH + hh) * NN + row0) * HID + f;
    const u64 z2 = pack2(0.f, 0.f);
    for (int r = 0; r < 32; r += 2) {
        const ulonglong2* xr0 = (const ulonglong2*)(xs + r * FIN);
        const ulonglong2* xr1 = (const ulonglong2*)(xs + (r + 1) * FIN);
        u64 aA0 = z2, aB0 = z2, aA1 = z2, aB1 = z2;
#pragma unroll
        for (int q = 0; q < 16; q++) {
            ulonglong2 x0 = xr0[q], x1 = xr1[q];
            ffma2(aA0, x0.x, w1p[2 * q]);
            ffma2(aB0, x0.y, w1p[2 * q + 1]);
            ffma2(aA1, x1.x, w1p[2 * q]);
            ffma2(aB1, x1.y, w1p[2 * q + 1]);
        }
        float2 fa0 = unpack2(aA0), fb0 = unpack2(aB0);
        float2 fa1 = unpack2(aA1), fb1 = unpack2(aB1);
        float acc0 = (fa0.x + fa0.y) + (fb0.x + fb0.y);
        float acc1 = (fa1.x + fa1.y) + (fb1.x + fb1.y);
        hs[r * HS_STRIDE + t]       = acc0;
        hs[(r + 1) * HS_STRIDE + t] = acc1;
        __nv_bfloat16 h0 = __float2bfloat16(acc0);
        __nv_bfloat16 h1 = __float2bfloat16(acc1);
        phi[(size_t)r * HID]       = h0;
        phi[(size_t)(r + 1) * HID] = h1;
        plo[(size_t)r * HID]       = __float2bfloat16(acc0 - __bfloat162float(h0));
        plo[(size_t)(r + 1) * HID] = __float2bfloat16(acc1 - __bfloat162float(h1));
    }
    __syncthreads();

    {   // e1: thread t -> row = t>>3, h = (t>>1)&3, vec = t&1
        const int row = t >> 3, h = (t >> 1) & 3, vec = t & 1;
        const float4* hp = (const float4*)(hs + row * HS_STRIDE + h * HID);
        const float4* ap = (const float4*)(av + vec * HF + h * HID);
        float s = 0.f;
#pragma unroll
        for (int j = 0; j < 16; j++) {
            float4 hv = hp[j], aw = ap[j];
            s += hv.x * aw.x + hv.y * aw.y + hv.z * aw.z + hv.w * aw.w;
        }
        int idx = (b * NH + h) * NN + row0 + row;
        if (vec == 0) g_E1s[idx] = s; else g_E1d[idx] = s;
    }
}

// ---------------------------------------------------------------------------
// Kernel M: bit-pack adjacency masks. mask[d][s] = adj[s][d]!=0 || d==s.
// ---------------------------------------------------------------------------
__global__ void __launch_bounds__(256) kM(const int* __restrict__ adj) {
    const int b = blockIdx.x, tile = blockIdx.y, d0 = tile * 128;
    const int t = threadIdx.x, lane = t & 31, warp = t >> 5;
    const int* ab = adj + (size_t)b * NN * NN;
    for (int s = warp; s < NN; s += 8) {
#pragma unroll
        for (int w = 0; w < 4; w++) {
            int d = d0 + w * 32 + lane;
            int a = ab[s * NN + d];
            unsigned m = __ballot_sync(0xffffffffu, (a != 0) || (s == d));
            if (lane == 0) g_mask[(((b * 4 + tile) * NN) + s) * 4 + w] = m;
        }
    }
}

// ---------------------------------------------------------------------------
// kAgg1: layer-1 masked-softmax aggregation via mma.sync (bf16 hi/lo split),
// fragment loads via ldmatrix. Grid (32, 4 tiles, 4 heads). 256 thr, 3 CTA/SM.
// ---------------------------------------------------------------------------
__global__ void __launch_bounds__(256, 3) kAgg1(const float* __restrict__ b1) {
    extern __shared__ __align__(16) char sm[];
    float* esS  = (float*)(sm + AG_ES);
    float* edS  = (float*)(sm + AG_ED);
    u32*   mskS = (u32*)  (sm + AG_MSK);
    float* zpS  = (float*)(sm + AG_ZP);
    const u32 smB = smem_u32(sm);

    const int b = blockIdx.x, tile = blockIdx.y, head = blockIdx.z;
    const int d0 = tile * 128;
    const int t = threadIdx.x, lane = t & 31, warp = t >> 5;

    for (int i = t; i < NN; i += 256) esS[i] = g_E1s[(b * NH + head) * NN + i];
    if (t < 128) edS[t] = g_E1d[(b * NH + head) * NN + d0 + t];
    for (int i = t; i < NN * 4; i += 256)
        mskS[i] = g_mask[((b * 4 + tile) * NN) * 4 + i];
    __syncthreads();

    // fill mapping
    const int dF = t >> 1, half = t & 1;
    const float edv = edS[dF];
    const u32 mybit = 1u << (dF & 31);
    const int mw = dF >> 5;
    u32* ahF = (u32*)(sm + AG_AH + dF * (SA * 2) + half * 64);
    u32* alF = (u32*)(sm + AG_AL + dF * (SA * 2) + half * 64);

    // Ht copy mapping
    const int sH = t >> 2, fg = t & 3;

    // ldmatrix lane addresses
    const int g = lane >> 2, tig = lane & 3;
    const u32 aAh = smB + AG_AH + (warp * 16 + (lane & 15)) * (SA * 2)
                  + ((lane >> 4) * 16);
    const u32 aAl = aAh + (AG_AL - AG_AH);
    const u32 bBase = smB + ((lane < 16) ? AG_HTH : AG_HTL)
                    + (lane & 7) * (ST * 2) + ((lane >> 3) & 1) * 16;

    float acc[32];
#pragma unroll
    for (int i = 0; i < 32; i++) acc[i] = 0.f;
    float z = 0.f;

    for (int ck = 0; ck < 8; ck++) {
        const int s0 = ck * 64;
        // ---- alpha fill (trunc-split bf16 hi/lo) ----
#pragma unroll
        for (int i = 0; i < 16; i++) {
            int s = s0 + half * 32 + 2 * i;
            float sc0 = edv + esS[s];
            float sc1 = edv + esS[s + 1];
            sc0 = fmaxf(sc0, 0.2f * sc0);
            sc1 = fmaxf(sc1, 0.2f * sc1);
            float w0 = (mskS[s * 4 + mw] & mybit) ? __expf(sc0) : 0.f;
            float w1 = (mskS[(s + 1) * 4 + mw] & mybit) ? __expf(sc1) : 0.f;
            z += w0 + w1;
            u32 f0 = __float_as_uint(w0), f1 = __float_as_uint(w1);
            float h0 = __uint_as_float(f0 & 0xFFFF0000u);
            float h1 = __uint_as_float(f1 & 0xFFFF0000u);
            ahF[i] = __byte_perm(f0, f1, 0x7632);
            alF[i] = __byte_perm(__float_as_uint(w0 - h0),
                                 __float_as_uint(w1 - h1), 0x7632);
        }
        // ---- Ht copy (transpose to [f][s], stride ST) ----
        {
            const __nv_bfloat16* srch =
                g_B1hi + ((size_t)(b * NH + head) * NN + s0 + sH) * HID + fg * 16;
            const __nv_bfloat16* srcl =
                g_B1lo + ((size_t)(b * NH + head) * NN + s0 + sH) * HID + fg * 16;
            uint4 vh[2], vl[2];
            vh[0] = ((const uint4*)srch)[0]; vh[1] = ((const uint4*)srch)[1];
            vl[0] = ((const uint4*)srcl)[0]; vl[1] = ((const uint4*)srcl)[1];
            const __nv_bfloat16* eh = (const __nv_bfloat16*)vh;
            const __nv_bfloat16* el = (const __nv_bfloat16*)vl;
            __nv_bfloat16* Hth = (__nv_bfloat16*)(sm + AG_HTH);
            __nv_bfloat16* Htl = (__nv_bfloat16*)(sm + AG_HTL);
#pragma unroll
            for (int j = 0; j < 16; j++) {
                int f = fg * 16 + j;
                Hth[f * ST + sH] = eh[j];
                Htl[f * ST + sH] = el[j];
            }
        }
        __syncthreads();

        // ---- mma: 4 ksteps x 8 n-tiles x 3 terms, ldmatrix frag loads ----
#pragma unroll
        for (int ks = 0; ks < 4; ks++) {
            u32 ah[4], al[4];
            ldsm_x4(ah[0], ah[1], ah[2], ah[3], aAh + ks * 32);
            ldsm_x4(al[0], al[1], al[2], al[3], aAl + ks * 32);
#pragma unroll
            for (int nt = 0; nt < 8; nt++) {
                u32 bh0, bh1, bl0, bl1;   // combined hi/lo in one x4
                ldsm_x4(bh0, bh1, bl0, bl1, bBase + nt * (8 * ST * 2) + ks * 32);
                mma16816(acc + nt * 4, ah, bh0, bh1);
                mma16816(acc + nt * 4, ah, bl0, bl1);
                mma16816(acc + nt * 4, al, bh0, bh1);
            }
        }
        __syncthreads();
    }

    // ---- epilogue: Z, normalize, +b1, ELU -> g_T1 ----
    zpS[t] = z;
    __syncthreads();
    const int r0 = warp * 16 + g, r1 = r0 + 8;
    const float rZ0 = 1.0f / (zpS[2 * r0] + zpS[2 * r0 + 1]);
    const float rZ1 = 1.0f / (zpS[2 * r1] + zpS[2 * r1 + 1]);
    float* o0 = g_T1 + ((size_t)(b * NN + d0 + r0)) * HF + head * 64;
    float* o1 = g_T1 + ((size_t)(b * NN + d0 + r1)) * HF + head * 64;
#pragma unroll
    for (int nt = 0; nt < 8; nt++) {
        int cb = nt * 8 + 2 * tig;
        float2 bv = *(const float2*)(b1 + head * 64 + cb);
        float v0 = acc[nt * 4 + 0] * rZ0 + bv.x;
        float v1 = acc[nt * 4 + 1] * rZ0 + bv.y;
        float v2 = acc[nt * 4 + 2] * rZ1 + bv.x;
        float v3 = acc[nt * 4 + 3] * rZ1 + bv.y;
        v0 = v0 > 0.f ? v0 : (__expf(v0) - 1.f);
        v1 = v1 > 0.f ? v1 : (__expf(v1) - 1.f);
        v2 = v2 > 0.f ? v2 : (__expf(v2) - 1.f);
        v3 = v3 > 0.f ? v3 : (__expf(v3) - 1.f);
        *(float2*)(o0 + cb) = make_float2(v0, v1);
        *(float2*)(o1 + cb) = make_float2(v2, v3);
    }
}

// ---------------------------------------------------------------------------
// kP: proj2 with W2 staged through smem (64-row chunks) + e2 + bf16 hi/lo H2.
// ---------------------------------------------------------------------------
#define H2S_STRIDE 72
#define KP_OFF_W2  32768
#define KP_OFF_H2S 49152
#define KP_SMEM    (49152 + 32 * H2S_STRIDE * 4)

__global__ void __launch_bounds__(256) kP(const float* __restrict__ W2,
                                          const float* __restrict__ a2s,
                                          const float* __restrict__ a2d) {
    extern __shared__ __align__(16) char smp[];
    float* tile = (float*)smp;
    float* w2s  = (float*)(smp + KP_OFF_W2);
    float* h2s  = (float*)(smp + KP_OFF_H2S);
    const int b = blockIdx.x, n0 = blockIdx.y * 32;
    const int t = threadIdx.x;

    const float4* src = (const float4*)(g_T1 + ((size_t)(b * NN + n0)) * HF);
    for (int i = t; i < 32 * HF / 4; i += 256) ((float4*)tile)[i] = src[i];

    const int o = t & 63, grp = t >> 6;
    u64 accA[8], accB[8];
#pragma unroll
    for (int i = 0; i < 8; i++) { accA[i] = pack2(0.f, 0.f); accB[i] = pack2(0.f, 0.f); }

    for (int cc = 0; cc < 4; cc++) {
        if (cc) __syncthreads();
        const float4* wsrc = (const float4*)(W2 + cc * 64 * FOUT);
        for (int i = t; i < 64 * FOUT / 4; i += 256) ((float4*)w2s)[i] = wsrc[i];
        __syncthreads();
#pragma unroll
        for (int cl = 0; cl < 64; cl += 4) {
            const int c = cc * 64 + cl;
            u64 wpA = pack2(w2s[cl * FOUT + o],       w2s[(cl + 1) * FOUT + o]);
            u64 wpB = pack2(w2s[(cl + 2) * FOUT + o], w2s[(cl + 3) * FOUT + o]);
#pragma unroll
            for (int i = 0; i < 8; i++) {
                ulonglong2 tv = *(const ulonglong2*)(tile + (grp * 8 + i) * HF + c);
                ffma2(accA[i], tv.x, wpA);
                ffma2(accB[i], tv.y, wpB);
            }
        }
    }
#pragma unroll
    for (int i = 0; i < 8; i++) {
        float2 va = unpack2(accA[i]), vb = unpack2(accB[i]);
        float v = (va.x + va.y) + (vb.x + vb.y);
        int d = grp * 8 + i;
        size_t gi = ((size_t)(b * NN + n0 + d)) * FOUT + o;
        __nv_bfloat16 hi = __float2bfloat16(v);
        g_B2hi[gi] = hi;
        g_B2lo[gi] = __float2bfloat16(v - __bfloat162float(hi));
        h2s[d * H2S_STRIDE + o] = v;
    }
    __syncthreads();

    if (t < 64) {
        const int node = t >> 1, vec = t & 1;
        const float* aw = vec ? a2d : a2s;
        const float4* hp = (const float4*)(h2s + node * H2S_STRIDE);
        float s = 0.f;
#pragma unroll
        for (int j = 0; j < 16; j++) {
            float4 hv = hp[j];
            s += hv.x * aw[4 * j] + hv.y * aw[4 * j + 1]
               + hv.z * aw[4 * j + 2] + hv.w * aw[4 * j + 3];
        }
        int idx = b * NN + n0 + node;
        if (vec == 0) g_E2s[idx] = s; else g_E2d[idx] = s;
    }
}

// ---------------------------------------------------------------------------
// kAgg2: layer-2 aggregation via mma.sync + b2 -> out. Grid (32, 4, 2):
// z splits 64 cols into 32-col halves. ldmatrix frag loads.
// ---------------------------------------------------------------------------
__global__ void __launch_bounds__(256, 3) kAgg2(const float* __restrict__ b2,
                                                float* __restrict__ out) {
    extern __shared__ __align__(16) char sm[];
    float* esS  = (float*)(sm + AG_ES);
    float* edS  = (float*)(sm + AG_ED);
    u32*   mskS = (u32*)  (sm + AG_MSK);
    float* zpS  = (float*)(sm + AG_ZP);
    const u32 smB = smem_u32(sm);

    const int b = blockIdx.x, tile = blockIdx.y, ncol0 = blockIdx.z * 32;
    const int d0 = tile * 128;
    const int t = threadIdx.x, lane = t & 31, warp = t >> 5;

    for (int i = t; i < NN; i += 256) esS[i] = g_E2s[b * NN + i];
    if (t < 128) edS[t] = g_E2d[b * NN + d0 + t];
    for (int i = t; i < NN * 4; i += 256)
        mskS[i] = g_mask[((b * 4 + tile) * NN) * 4 + i];
    __syncthreads();

    const int dF = t >> 1, half = t & 1;
    const float edv = edS[dF];
    const u32 mybit = 1u << (dF & 31);
    const int mw = dF >> 5;
    u32* ahF = (u32*)(sm + AG_AH + dF * (SA * 2) + half * 64);
    u32* alF = (u32*)(sm + AG_AL + dF * (SA * 2) + half * 64);

    const int g = lane >> 2, tig = lane & 3;
    const u32 aAh = smB + AG_AH + (warp * 16 + (lane & 15)) * (SA * 2)
                  + ((lane >> 4) * 16);
    const u32 aAl = aAh + (AG_AL - AG_AH);
    const u32 bBase = smB + ((lane < 16) ? AG_HTH : AG_HTL)
                    + (lane & 7) * (ST * 2) + ((lane >> 3) & 1) * 16;

    float acc[16];
#pragma unroll
    for (int i = 0; i < 16; i++) acc[i] = 0.f;
    float z = 0.f;

    for (int ck = 0; ck < 8; ck++) {
        const int s0 = ck * 64;
#pragma unroll
        for (int i = 0; i < 16; i++) {
            int s = s0 + half * 32 + 2 * i;
            float sc0 = edv + esS[s];
            float sc1 = edv + esS[s + 1];
            sc0 = fmaxf(sc0, 0.2f * sc0);
            sc1 = fmaxf(sc1, 0.2f * sc1);
            float w0 = (mskS[s * 4 + mw] & mybit) ? __expf(sc0) : 0.f;
            float w1 = (mskS[(s + 1) * 4 + mw] & mybit) ? __expf(sc1) : 0.f;
            z += w0 + w1;
            u32 f0 = __float_as_uint(w0), f1 = __float_as_uint(w1);
            float h0 = __uint_as_float(f0 & 0xFFFF0000u);
            float h1 = __uint_as_float(f1 & 0xFFFF0000u);
            ahF[i] = __byte_perm(f0, f1, 0x7632);
            alF[i] = __byte_perm(__float_as_uint(w0 - h0),
                                 __float_as_uint(w1 - h1), 0x7632);
        }
        if (t < 128) {   // Ht copy: 32 cols (this z-half), 64 s rows
            const int sH2 = t >> 1, fg2 = t & 1;
            const __nv_bfloat16* srch =
                g_B2hi + ((size_t)(b * NN + s0 + sH2)) * FOUT + ncol0 + fg2 * 16;
            const __nv_bfloat16* srcl =
                g_B2lo + ((size_t)(b * NN + s0 + sH2)) * FOUT + ncol0 + fg2 * 16;
            uint4 vh[2], vl[2];
            vh[0] = ((const uint4*)srch)[0]; vh[1] = ((const uint4*)srch)[1];
            vl[0] = ((const uint4*)srcl)[0]; vl[1] = ((const uint4*)srcl)[1];
            const __nv_bfloat16* eh = (const __nv_bfloat16*)vh;
            const __nv_bfloat16* el = (const __nv_bfloat16*)vl;
            __nv_bfloat16* Hth = (__nv_bfloat16*)(sm + AG_HTH);
            __nv_bfloat16* Htl = (__nv_bfloat16*)(sm + AG_HTL);
#pragma unroll
            for (int j = 0; j < 16; j++) {
                int f = fg2 * 16 + j;
                Hth[f * ST + sH2] = eh[j];
                Htl[f * ST + sH2] = el[j];
            }
        }
        __syncthreads();

#pragma unroll
        for (int ks = 0; ks < 4; ks++) {
            u32 ah[4], al[4];
            ldsm_x4(ah[0], ah[1], ah[2], ah[3], aAh + ks * 32);
            ldsm_x4(al[0], al[1], al[2], al[3], aAl + ks * 32);
#pragma unroll
            for (int nt = 0; nt < 4; nt++) {
                u32 bh0, bh1, bl0, bl1;
                ldsm_x4(bh0, bh1, bl0, bl1, bBase + nt * (8 * ST * 2) + ks * 32);
                mma16816(acc + nt * 4, ah, bh0, bh1);
                mma16816(acc + nt * 4, ah, bl0, bl1);
                mma16816(acc + nt * 4, al, bh0, bh1);
            }
        }
        __syncthreads();
    }

    zpS[t] = z;
    __syncthreads();
    const int r0 = warp * 16 + g, r1 = r0 + 8;
    const float rZ0 = 1.0f / (zpS[2 * r0] + zpS[2 * r0 + 1]);
    const float rZ1 = 1.0f / (zpS[2 * r1] + zpS[2 * r1 + 1]);
    float* o0 = out + ((size_t)(b * NN + d0 + r0)) * FOUT + ncol0;
    float* o1 = out + ((size_t)(b * NN + d0 + r1)) * FOUT + ncol0;
#pragma unroll
    for (int nt = 0; nt < 4; nt++) {
        int cb = nt * 8 + 2 * tig;
        float2 bv = *(const float2*)(b2 + ncol0 + cb);
        *(float2*)(o0 + cb) = make_float2(acc[nt * 4 + 0] * rZ0 + bv.x,
                                          acc[nt * 4 + 1] * rZ0 + bv.y);
        *(float2*)(o1 + cb) = make_float2(acc[nt * 4 + 2] * rZ1 + bv.x,
                                          acc[nt * 4 + 3] * rZ1 + bv.y);
    }
}

// ---------------------------------------------------------------------------
extern "C" void kernel_launch(void* const* d_in, const int* in_sizes, int n_in,
                              void* d_out, int out_size) {
    const float* x   = (const float*)d_in[0];
    const int*   adj = (const int*)  d_in[1];
    const float* W1  = (const float*)d_in[2];
    const float* a1s = (const float*)d_in[3];
    const float* a1d = (const float*)d_in[4];
    const float* b1  = (const float*)d_in[5];
    const float* W2  = (const float*)d_in[6];
    const float* a2s = (const float*)d_in[7];
    const float* a2d = (const float*)d_in[8];
    const float* b2  = (const float*)d_in[9];
    float* out = (float*)d_out;

    cudaFuncSetAttribute(kAgg1, cudaFuncAttributeMaxDynamicSharedMemorySize, AG_SMEM);
    cudaFuncSetAttribute(kAgg2, cudaFuncAttributeMaxDynamicSharedMemorySize, AG_SMEM);
    cudaFuncSetAttribute(kP,    cudaFuncAttributeMaxDynamicSharedMemorySize, KP_SMEM);

    kA   <<<dim3(NB, 16), 256>>>(x, W1, a1s, a1d);
    kM   <<<dim3(NB, 4),  256>>>(adj);
    kAgg1<<<dim3(NB, 4, NH), 256, AG_SMEM>>>(b1);
    kP   <<<dim3(NB, 16), 256, KP_SMEM>>>(W2, a2s, a2d);
    kAgg2<<<dim3(NB, 4, 2), 256, AG_SMEM>>>(b2, out);
}

// round 12
// speedup vs baseline: 1.4333x; 1.0097x over previous
#include <cuda_runtime.h>
#include <cuda_bf16.h>
#include <cstdint>

// Problem constants
#define NB   32
#define NN   512
#define FIN  64
#define NH   4
#define HID  64
#define HF   256   // NH*HID
#define FOUT 64

typedef unsigned long long u64;
typedef unsigned int       u32;

// ---------------- scratch (static device arrays; no allocation) -------------
__device__ __nv_bfloat16 g_B1hi[NB * NH * NN * HID];   // H1 split, [b,h,s,f]
__device__ __nv_bfloat16 g_B1lo[NB * NH * NN * HID];
__device__ __nv_bfloat16 g_B2hi[NB * NN * FOUT];       // H2 split, [b,s,f]
__device__ __nv_bfloat16 g_B2lo[NB * NN * FOUT];
__device__ float g_T1[NB * NN * HF];                   // elu(agg1)+b1, fp32
__device__ u32   g_mask[NB * 4 * NN * 4];              // [b,tile128,s,word4]
__device__ float g_E1s[NB * NH * NN], g_E1d[NB * NH * NN];   // [b,h,s]
__device__ float g_E2s[NB * NN],      g_E2d[NB * NN];

// ---------------- packed f32x2 helpers ---------------------------------------
__device__ __forceinline__ void ffma2(u64& d, u64 a, u64 b) {
    asm("fma.rn.f32x2 %0, %1, %2, %0;" : "+l"(d) : "l"(a), "l"(b));
}
__device__ __forceinline__ u64 pack2(float x, float y) {
    u64 r; asm("mov.b64 %0, {%1, %2};" : "=l"(r) : "f"(x), "f"(y)); return r;
}
__device__ __forceinline__ float2 unpack2(u64 v) {
    float2 r; asm("mov.b64 {%0, %1}, %2;" : "=f"(r.x), "=f"(r.y) : "l"(v)); return r;
}

// ---------------- mma.sync m16n8k16 bf16 + ldmatrix --------------------------
__device__ __forceinline__ void mma16816(float* c, const u32* a, u32 b0, u32 b1) {
    asm volatile(
        "mma.sync.aligned.m16n8k16.row.col.f32.bf16.bf16.f32 "
        "{%0,%1,%2,%3}, {%4,%5,%6,%7}, {%8,%9}, {%0,%1,%2,%3};"
        : "+f"(c[0]), "+f"(c[1]), "+f"(c[2]), "+f"(c[3])
        : "r"(a[0]), "r"(a[1]), "r"(a[2]), "r"(a[3]), "r"(b0), "r"(b1));
}
__device__ __forceinline__ void ldsm_x4(u32& r0, u32& r1, u32& r2, u32& r3, u32 addr) {
    asm volatile("ldmatrix.sync.aligned.m8n8.x4.shared.b16 {%0,%1,%2,%3}, [%4];"
                 : "=r"(r0), "=r"(r1), "=r"(r2), "=r"(r3) : "r"(addr));
}
__device__ __forceinline__ u32 smem_u32(const void* p) {
    u32 a; asm("{ .reg .u64 t; cvta.to.shared.u64 t, %1; cvt.u32.u64 %0, t; }"
               : "=r"(a) : "l"(p));
    return a;
}

// smem layout for aggregation kernels (byte offsets)
#define SA     72    // alpha row stride (bf16 elems): 144B = 36 words
#define ST     72    // Ht row stride
#define AG_AH  0
#define AG_AL  18432
#define AG_HTH 36864
#define AG_HTL 46080
#define AG_ES  55296
#define AG_ED  57344
#define AG_MSK 57856
#define AG_ZP  66048
#define AG_SMEM 67072

// ---------------------------------------------------------------------------
// Kernel A: H1 = x @ W1 (emitted bf16 hi/lo per-head [b,h,s,f]) + e1 [b,h,s].
// ---------------------------------------------------------------------------
#define HS_STRIDE 264

__global__ void __launch_bounds__(256, 2) kA(const float* __restrict__ x,
                                             const float* __restrict__ W1,
                                             const float* __restrict__ a1s,
                                             const float* __restrict__ a1d) {
    __shared__ __align__(16) float xs[32 * FIN];
    __shared__ __align__(16) float hs[32 * HS_STRIDE];
    __shared__ __align__(16) float av[2 * HF];

    const int b = blockIdx.x, row0 = blockIdx.y * 32;
    const int t = threadIdx.x;

    const float* xp = x + ((size_t)(b * NN + row0)) * FIN;
    for (int i = t; i < 32 * FIN; i += 256) xs[i] = xp[i];
    av[t]      = a1s[t];
    av[t + HF] = a1d[t];

    u64 w1p[32];
#pragma unroll
    for (int kk = 0; kk < 32; kk++)
        w1p[kk] = pack2(W1[(2 * kk) * HF + t], W1[(2 * kk + 1) * HF + t]);
    __syncthreads();

    const int hh = t >> 6, f = t & 63;
    __nv_bfloat16* phi = g_B1hi + ((size_t)(b * NH + hh) * NN + row0) * HID + f;
    __nv_bfloat16* plo = g_B1lo + ((size_t)(b * NH + hh) * NN + row0) * HID + f;
    const u64 z2 = pack2(0.f, 0.f);
    for (int r = 0; r < 32; r += 2) {
        const ulonglong2* xr0 = (const ulonglong2*)(xs + r * FIN);
        const ulonglong2* xr1 = (const ulonglong2*)(xs + (r + 1) * FIN);
        u64 aA0 = z2, aB0 = z2, aA1 = z2, aB1 = z2;
#pragma unroll
        for (int q = 0; q < 16; q++) {
            ulonglong2 x0 = xr0[q], x1 = xr1[q];
            ffma2(aA0, x0.x, w1p[2 * q]);
            ffma2(aB0, x0.y, w1p[2 * q + 1]);
            ffma2(aA1, x1.x, w1p[2 * q]);
            ffma2(aB1, x1.y, w1p[2 * q + 1]);
        }
        float2 fa0 = unpack2(aA0), fb0 = unpack2(aB0);
        float2 fa1 = unpack2(aA1), fb1 = unpack2(aB1);
        float acc0 = (fa0.x + fa0.y) + (fb0.x + fb0.y);
        float acc1 = (fa1.x + fa1.y) + (fb1.x + fb1.y);
        hs[r * HS_STRIDE + t]       = acc0;
        hs[(r + 1) * HS_STRIDE + t] = acc1;
        __nv_bfloat16 h0 = __float2bfloat16(acc0);
        __nv_bfloat16 h1 = __float2bfloat16(acc1);
        phi[(size_t)r * HID]       = h0;
        phi[(size_t)(r + 1) * HID] = h1;
        plo[(size_t)r * HID]       = __float2bfloat16(acc0 - __bfloat162float(h0));
        plo[(size_t)(r + 1) * HID] = __float2bfloat16(acc1 - __bfloat162float(h1));
    }
    __syncthreads();

    {   // e1: thread t -> row = t>>3, h = (t>>1)&3, vec = t&1
        const int row = t >> 3, h = (t >> 1) & 3, vec = t & 1;
        const float4* hp = (const float4*)(hs + row * HS_STRIDE + h * HID);
        const float4* ap = (const float4*)(av + vec * HF + h * HID);
        float s = 0.f;
#pragma unroll
        for (int j = 0; j < 16; j++) {
            float4 hv = hp[j], aw = ap[j];
            s += hv.x * aw.x + hv.y * aw.y + hv.z * aw.z + hv.w * aw.w;
        }
        int idx = (b * NH + h) * NN + row0 + row;
        if (vec == 0) g_E1s[idx] = s; else g_E1d[idx] = s;
    }
}

// ---------------------------------------------------------------------------
// Kernel M: bit-pack adjacency masks. mask[d][s] = adj[s][d]!=0 || d==s.
// ---------------------------------------------------------------------------
__global__ void __launch_bounds__(256) kM(const int* __restrict__ adj) {
    const int b = blockIdx.x, tile = blockIdx.y, d0 = tile * 128;
    const int t = threadIdx.x, lane = t & 31, warp = t >> 5;
    const int* ab = adj + (size_t)b * NN * NN;
    for (int s = warp; s < NN; s += 8) {
#pragma unroll
        for (int w = 0; w < 4; w++) {
            int d = d0 + w * 32 + lane;
            int a = ab[s * NN + d];
            unsigned m = __ballot_sync(0xffffffffu, (a != 0) || (s == d));
            if (lane == 0) g_mask[(((b * 4 + tile) * NN) + s) * 4 + w] = m;
        }
    }
}

// ---------------------------------------------------------------------------
// kAgg1: layer-1 masked-softmax aggregation via mma.sync (bf16 hi/lo split),
// ldmatrix frag loads. Grid (32, 4 tiles, 4 heads). 256 thr, 2 CTAs/SM
// (128-reg cap: 32 fp32 accumulators must stay in registers — at 3 CTAs/SM
// the 85-reg cap spills them into the hot loop).
// ---------------------------------------------------------------------------
__global__ void __launch_bounds__(256, 2) kAgg1(const float* __restrict__ b1) {
    extern __shared__ __align__(16) char sm[];
    float* esS  = (float*)(sm + AG_ES);
    float* edS  = (float*)(sm + AG_ED);
    u32*   mskS = (u32*)  (sm + AG_MSK);
    float* zpS  = (float*)(sm + AG_ZP);
    const u32 smB = smem_u32(sm);

    const int b = blockIdx.x, tile = blockIdx.y, head = blockIdx.z;
    const int d0 = tile * 128;
    const int t = threadIdx.x, lane = t & 31, warp = t >> 5;

    for (int i = t; i < NN; i += 256) esS[i] = g_E1s[(b * NH + head) * NN + i];
    if (t < 128) edS[t] = g_E1d[(b * NH + head) * NN + d0 + t];
    for (int i = t; i < NN * 4; i += 256)
        mskS[i] = g_mask[((b * 4 + tile) * NN) * 4 + i];
    __syncthreads();

    // fill mapping
    const int dF = t >> 1, half = t & 1;
    const float edv = edS[dF];
    const u32 mybit = 1u << (dF & 31);
    const int mw = dF >> 5;
    u32* ahF = (u32*)(sm + AG_AH + dF * (SA * 2) + half * 64);
    u32* alF = (u32*)(sm + AG_AL + dF * (SA * 2) + half * 64);

    // Ht copy mapping
    const int sH = t >> 2, fg = t & 3;

    // ldmatrix lane addresses
    const int g = lane >> 2, tig = lane & 3;
    const u32 aAh = smB + AG_AH + (warp * 16 + (lane & 15)) * (SA * 2)
                  + ((lane >> 4) * 16);
    const u32 aAl = aAh + (AG_AL - AG_AH);
    const u32 bBase = smB + ((lane < 16) ? AG_HTH : AG_HTL)
                    + (lane & 7) * (ST * 2) + ((lane >> 3) & 1) * 16;

    float acc[32];
#pragma unroll
    for (int i = 0; i < 32; i++) acc[i] = 0.f;
    float z = 0.f;

    for (int ck = 0; ck < 8; ck++) {
        const int s0 = ck * 64;
        // ---- alpha fill (trunc-split bf16 hi/lo) ----
#pragma unroll
        for (int i = 0; i < 16; i++) {
            int s = s0 + half * 32 + 2 * i;
            float sc0 = edv + esS[s];
            float sc1 = edv + esS[s + 1];
            sc0 = fmaxf(sc0, 0.2f * sc0);
            sc1 = fmaxf(sc1, 0.2f * sc1);
            float w0 = (mskS[s * 4 + mw] & mybit) ? __expf(sc0) : 0.f;
            float w1 = (mskS[(s + 1) * 4 + mw] & mybit) ? __expf(sc1) : 0.f;
            z += w0 + w1;
            u32 f0 = __float_as_uint(w0), f1 = __float_as_uint(w1);
            float h0 = __uint_as_float(f0 & 0xFFFF0000u);
            float h1 = __uint_as_float(f1 & 0xFFFF0000u);
            ahF[i] = __byte_perm(f0, f1, 0x7632);
            alF[i] = __byte_perm(__float_as_uint(w0 - h0),
                                 __float_as_uint(w1 - h1), 0x7632);
        }
        // ---- Ht copy (transpose to [f][s], stride ST) ----
        {
            const __nv_bfloat16* srch =
                g_B1hi + ((size_t)(b * NH + head) * NN + s0 + sH) * HID + fg * 16;
            const __nv_bfloat16* srcl =
                g_B1lo + ((size_t)(b * NH + head) * NN + s0 + sH) * HID + fg * 16;
            uint4 vh[2], vl[2];
            vh[0] = ((const uint4*)srch)[0]; vh[1] = ((const uint4*)srch)[1];
            vl[0] = ((const uint4*)srcl)[0]; vl[1] = ((const uint4*)srcl)[1];
            const __nv_bfloat16* eh = (const __nv_bfloat16*)vh;
            const __nv_bfloat16* el = (const __nv_bfloat16*)vl;
            __nv_bfloat16* Hth = (__nv_bfloat16*)(sm + AG_HTH);
            __nv_bfloat16* Htl = (__nv_bfloat16*)(sm + AG_HTL);
#pragma unroll
            for (int j = 0; j < 16; j++) {
                int f = fg * 16 + j;
                Hth[f * ST + sH] = eh[j];
                Htl[f * ST + sH] = el[j];
            }
        }
        __syncthreads();

        // ---- mma: 4 ksteps x 8 n-tiles x 3 terms, ldmatrix frag loads ----
#pragma unroll
        for (int ks = 0; ks < 4; ks++) {
            u32 ah[4], al[4];
            ldsm_x4(ah[0], ah[1], ah[2], ah[3], aAh + ks * 32);
            ldsm_x4(al[0], al[1], al[2], al[3], aAl + ks * 32);
#pragma unroll
            for (int nt = 0; nt < 8; nt++) {
                u32 bh0, bh1, bl0, bl1;   // combined hi/lo in one x4
                ldsm_x4(bh0, bh1, bl0, bl1, bBase + nt * (8 * ST * 2) + ks * 32);
                mma16816(acc + nt * 4, ah, bh0, bh1);
                mma16816(acc + nt * 4, ah, bl0, bl1);
                mma16816(acc + nt * 4, al, bh0, bh1);
            }
        }
        __syncthreads();
    }

    // ---- epilogue: Z, normalize, +b1, ELU -> g_T1 ----
    zpS[t] = z;
    __syncthreads();
    const int r0 = warp * 16 + g, r1 = r0 + 8;
    const float rZ0 = 1.0f / (zpS[2 * r0] + zpS[2 * r0 + 1]);
    const float rZ1 = 1.0f / (zpS[2 * r1] + zpS[2 * r1 + 1]);
    float* o0 = g_T1 + ((size_t)(b * NN + d0 + r0)) * HF + head * 64;
    float* o1 = g_T1 + ((size_t)(b * NN + d0 + r1)) * HF + head * 64;
#pragma unroll
    for (int nt = 0; nt < 8; nt++) {
        int cb = nt * 8 + 2 * tig;
        float2 bv = *(const float2*)(b1 + head * 64 + cb);
        float v0 = acc[nt * 4 + 0] * rZ0 + bv.x;
        float v1 = acc[nt * 4 + 1] * rZ0 + bv.y;
        float v2 = acc[nt * 4 + 2] * rZ1 + bv.x;
        float v3 = acc[nt * 4 + 3] * rZ1 + bv.y;
        v0 = v0 > 0.f ? v0 : (__expf(v0) - 1.f);
        v1 = v1 > 0.f ? v1 : (__expf(v1) - 1.f);
        v2 = v2 > 0.f ? v2 : (__expf(v2) - 1.f);
        v3 = v3 > 0.f ? v3 : (__expf(v3) - 1.f);
        *(float2*)(o0 + cb) = make_float2(v0, v1);
        *(float2*)(o1 + cb) = make_float2(v2, v3);
    }
}

// ---------------------------------------------------------------------------
// kP: proj2 with W2 staged through smem (64-row chunks) + e2 + bf16 hi/lo H2.
// ---------------------------------------------------------------------------
#define H2S_STRIDE 72
#define KP_OFF_W2  32768
#define KP_OFF_H2S 49152
#define KP_SMEM    (49152 + 32 * H2S_STRIDE * 4)

__global__ void __launch_bounds__(256) kP(const float* __restrict__ W2,
                                          const float* __restrict__ a2s,
                                          const float* __restrict__ a2d) {
    extern __shared__ __align__(16) char smp[];
    float* tile = (float*)smp;
    float* w2s  = (float*)(smp + KP_OFF_W2);
    float* h2s  = (float*)(smp + KP_OFF_H2S);
    const int b = blockIdx.x, n0 = blockIdx.y * 32;
    const int t = threadIdx.x;

    const float4* src = (const float4*)(g_T1 + ((size_t)(b * NN + n0)) * HF);
    for (int i = t; i < 32 * HF / 4; i += 256) ((float4*)tile)[i] = src[i];

    const int o = t & 63, grp = t >> 6;
    u64 accA[8], accB[8];
#pragma unroll
    for (int i = 0; i < 8; i++) { accA[i] = pack2(0.f, 0.f); accB[i] = pack2(0.f, 0.f); }

    for (int cc = 0; cc < 4; cc++) {
        if (cc) __syncthreads();
        const float4* wsrc = (const float4*)(W2 + cc * 64 * FOUT);
        for (int i = t; i < 64 * FOUT / 4; i += 256) ((float4*)w2s)[i] = wsrc[i];
        __syncthreads();
#pragma unroll
        for (int cl = 0; cl < 64; cl += 4) {
            const int c = cc * 64 + cl;
            u64 wpA = pack2(w2s[cl * FOUT + o],       w2s[(cl + 1) * FOUT + o]);
            u64 wpB = pack2(w2s[(cl + 2) * FOUT + o], w2s[(cl + 3) * FOUT + o]);
#pragma unroll
            for (int i = 0; i < 8; i++) {
                ulonglong2 tv = *(const ulonglong2*)(tile + (grp * 8 + i) * HF + c);
                ffma2(accA[i], tv.x, wpA);
                ffma2(accB[i], tv.y, wpB);
            }
        }
    }
#pragma unroll
    for (int i = 0; i < 8; i++) {
        float2 va = unpack2(accA[i]), vb = unpack2(accB[i]);
        float v = (va.x + va.y) + (vb.x + vb.y);
        int d = grp * 8 + i;
        size_t gi = ((size_t)(b * NN + n0 + d)) * FOUT + o;
        __nv_bfloat16 hi = __float2bfloat16(v);
        g_B2hi[gi] = hi;
        g_B2lo[gi] = __float2bfloat16(v - __bfloat162float(hi));
        h2s[d * H2S_STRIDE + o] = v;
    }
    __syncthreads();

    if (t < 64) {
        const int node = t >> 1, vec = t & 1;
        const float* aw = vec ? a2d : a2s;
        const float4* hp = (const float4*)(h2s + node * H2S_STRIDE);
        float s = 0.f;
#pragma unroll
        for (int j = 0; j < 16; j++) {
            float4 hv = hp[j];
            s += hv.x * aw[4 * j] + hv.y * aw[4 * j + 1]
               + hv.z * aw[4 * j + 2] + hv.w * aw[4 * j + 3];
        }
        int idx = b * NN + n0 + node;
        if (vec == 0) g_E2s[idx] = s; else g_E2d[idx] = s;
    }
}

// ---------------------------------------------------------------------------
// kAgg2: layer-2 aggregation via mma.sync + b2 -> out. Grid (32, 4, 2):
// z splits 64 cols into 32-col halves. ldmatrix frag loads. 2 CTAs/SM.
// ---------------------------------------------------------------------------
__global__ void __launch_bounds__(256, 2) kAgg2(const float* __restrict__ b2,
                                                float* __restrict__ out) {
    extern __shared__ __align__(16) char sm[];
    float* esS  = (float*)(sm + AG_ES);
    float* edS  = (float*)(sm + AG_ED);
    u32*   mskS = (u32*)  (sm + AG_MSK);
    float* zpS  = (float*)(sm + AG_ZP);
    const u32 smB = smem_u32(sm);

    const int b = blockIdx.x, tile = blockIdx.y, ncol0 = blockIdx.z * 32;
    const int d0 = tile * 128;
    const int t = threadIdx.x, lane = t & 31, warp = t >> 5;

    for (int i = t; i < NN; i += 256) esS[i] = g_E2s[b * NN + i];
    if (t < 128) edS[t] = g_E2d[b * NN + d0 + t];
    for (int i = t; i < NN * 4; i += 256)
        mskS[i] = g_mask[((b * 4 + tile) * NN) * 4 + i];
    __syncthreads();

    const int dF = t >> 1, half = t & 1;
    const float edv = edS[dF];
    const u32 mybit = 1u << (dF & 31);
    const int mw = dF >> 5;
    u32* ahF = (u32*)(sm + AG_AH + dF * (SA * 2) + half * 64);
    u32* alF = (u32*)(sm + AG_AL + dF * (SA * 2) + half * 64);

    const int g = lane >> 2, tig = lane & 3;
    const u32 aAh = smB + AG_AH + (warp * 16 + (lane & 15)) * (SA * 2)
                  + ((lane >> 4) * 16);
    const u32 aAl = aAh + (AG_AL - AG_AH);
    const u32 bBase = smB + ((lane < 16) ? AG_HTH : AG_HTL)
                    + (lane & 7) * (ST * 2) + ((lane >> 3) & 1) * 16;

    float acc[16];
#pragma unroll
    for (int i = 0; i < 16; i++) acc[i] = 0.f;
    float z = 0.f;

    for (int ck = 0; ck < 8; ck++) {
        const int s0 = ck * 64;
#pragma unroll
        for (int i = 0; i < 16; i++) {
            int s = s0 + half * 32 + 2 * i;
            float sc0 = edv + esS[s];
            float sc1 = edv + esS[s + 1];
            sc0 = fmaxf(sc0, 0.2f * sc0);
            sc1 = fmaxf(sc1, 0.2f * sc1);
            float w0 = (mskS[s * 4 + mw] & mybit) ? __expf(sc0) : 0.f;
            float w1 = (mskS[(s + 1) * 4 + mw] & mybit) ? __expf(sc1) : 0.f;
            z += w0 + w1;
            u32 f0 = __float_as_uint(w0), f1 = __float_as_uint(w1);
            float h0 = __uint_as_float(f0 & 0xFFFF0000u);
            float h1 = __uint_as_float(f1 & 0xFFFF0000u);
            ahF[i] = __byte_perm(f0, f1, 0x7632);
            alF[i] = __byte_perm(__float_as_uint(w0 - h0),
                                 __float_as_uint(w1 - h1), 0x7632);
        }
        if (t < 128) {   // Ht copy: 32 cols (this z-half), 64 s rows
            const int sH2 = t >> 1, fg2 = t & 1;
            const __nv_bfloat16* srch =
                g_B2hi + ((size_t)(b * NN + s0 + sH2)) * FOUT + ncol0 + fg2 * 16;
            const __nv_bfloat16* srcl =
                g_B2lo + ((size_t)(b * NN + s0 + sH2)) * FOUT + ncol0 + fg2 * 16;
            uint4 vh[2], vl[2];
            vh[0] = ((const uint4*)srch)[0]; vh[1] = ((const uint4*)srch)[1];
            vl[0] = ((const uint4*)srcl)[0]; vl[1] = ((const uint4*)srcl)[1];
            const __nv_bfloat16* eh = (const __nv_bfloat16*)vh;
            const __nv_bfloat16* el = (const __nv_bfloat16*)vl;
            __nv_bfloat16* Hth = (__nv_bfloat16*)(sm + AG_HTH);
            __nv_bfloat16* Htl = (__nv_bfloat16*)(sm + AG_HTL);
#pragma unroll
            for (int j = 0; j < 16; j++) {
                int f = fg2 * 16 + j;
                Hth[f * ST + sH2] = eh[j];
                Htl[f * ST + sH2] = el[j];
            }
        }
        __syncthreads();

#pragma unroll
        for (int ks = 0; ks < 4; ks++) {
            u32 ah[4], al[4];
            ldsm_x4(ah[0], ah[1], ah[2], ah[3], aAh + ks * 32);
            ldsm_x4(al[0], al[1], al[2], al[3], aAl + ks * 32);
#pragma unroll
            for (int nt = 0; nt < 4; nt++) {
                u32 bh0, bh1, bl0, bl1;
                ldsm_x4(bh0, bh1, bl0, bl1, bBase + nt * (8 * ST * 2) + ks * 32);
                mma16816(acc + nt * 4, ah, bh0, bh1);
                mma16816(acc + nt * 4, ah, bl0, bl1);
                mma16816(acc + nt * 4, al, bh0, bh1);
            }
        }
        __syncthreads();
    }

    zpS[t] = z;
    __syncthreads();
    const int r0 = warp * 16 + g, r1 = r0 + 8;
    const float rZ0 = 1.0f / (zpS[2 * r0] + zpS[2 * r0 + 1]);
    const float rZ1 = 1.0f / (zpS[2 * r1] + zpS[2 * r1 + 1]);
    float* o0 = out + ((size_t)(b * NN + d0 + r0)) * FOUT + ncol0;
    float* o1 = out + ((size_t)(b * NN + d0 + r1)) * FOUT + ncol0;
#pragma unroll
    for (int nt = 0; nt < 4; nt++) {
        int cb = nt * 8 + 2 * tig;
        float2 bv = *(const float2*)(b2 + ncol0 + cb);
        *(float2*)(o0 + cb) = make_float2(acc[nt * 4 + 0] * rZ0 + bv.x,
                                          acc[nt * 4 + 1] * rZ0 + bv.y);
        *(float2*)(o1 + cb) = make_float2(acc[nt * 4 + 2] * rZ1 + bv.x,
                                          acc[nt * 4 + 3] * rZ1 + bv.y);
    }
}

// ---------------------------------------------------------------------------
extern "C" void kernel_launch(void* const* d_in, const int* in_sizes, int n_in,
                              void* d_out, int out_size) {
    const float* x   = (const float*)d_in[0];
    const int*   adj = (const int*)  d_in[1];
    const float* W1  = (const float*)d_in[2];
    const float* a1s = (const float*)d_in[3];
    const float* a1d = (const float*)d_in[4];
    const float* b1  = (const float*)d_in[5];
    const float* W2  = (const float*)d_in[6];
    const float* a2s = (const float*)d_in[7];
    const float* a2d = (const float*)d_in[8];
    const float* b2  = (const float*)d_in[9];
    float* out = (float*)d_out;

    cudaFuncSetAttribute(kAgg1, cudaFuncAttributeMaxDynamicSharedMemorySize, AG_SMEM);
    cudaFuncSetAttribute(kAgg2, cudaFuncAttributeMaxDynamicSharedMemorySize, AG_SMEM);
    cudaFuncSetAttribute(kP,    cudaFuncAttributeMaxDynamicSharedMemorySize, KP_SMEM);

    kA   <<<dim3(NB, 16), 256>>>(x, W1, a1s, a1d);
    kM   <<<dim3(NB, 4),  256>>>(adj);
    kAgg1<<<dim3(NB, 4, NH), 256, AG_SMEM>>>(b1);
    kP   <<<dim3(NB, 16), 256, KP_SMEM>>>(W2, a2s, a2d);
    kAgg2<<<dim3(NB, 4, 2), 256, AG_SMEM>>>(b2, out);
}

// round 13
// speedup vs baseline: 1.9182x; 1.3383x over previous
#include <cuda_runtime.h>
#include <cuda_bf16.h>
#include <cuda_fp16.h>
#include <cstdint>

// Problem constants
#define NB   32
#define NN   512
#define FIN  64
#define NH   4
#define HID  64
#define HF   256   // NH*HID
#define FOUT 64

typedef unsigned long long u64;
typedef unsigned int       u32;

// ---------------- scratch (static device arrays; no allocation) -------------
__device__ __half g_B1h[NB * NH * NN * HID];   // H1 fp16, [b,h,s,f]
__device__ __half g_B2h[NB * NN * FOUT];       // H2 fp16, [b,s,f]
__device__ float g_T1[NB * NN * HF];           // elu(agg1)+b1, fp32
__device__ u32   g_mask[NB * 4 * NN * 4];      // [b,tile128,s,word4]
__device__ float g_E1s[NB * NH * NN], g_E1d[NB * NH * NN];   // [b,h,s]
__device__ float g_E2s[NB * NN],      g_E2d[NB * NN];

// ---------------- packed f32x2 helpers ---------------------------------------
__device__ __forceinline__ void ffma2(u64& d, u64 a, u64 b) {
    asm("fma.rn.f32x2 %0, %1, %2, %0;" : "+l"(d) : "l"(a), "l"(b));
}
__device__ __forceinline__ u64 pack2(float x, float y) {
    u64 r; asm("mov.b64 %0, {%1, %2};" : "=l"(r) : "f"(x), "f"(y)); return r;
}
__device__ __forceinline__ float2 unpack2(u64 v) {
    float2 r; asm("mov.b64 {%0, %1}, %2;" : "=f"(r.x), "=f"(r.y) : "l"(v)); return r;
}

// ---------------- mma.sync m16n8k16 fp16 + ldmatrix --------------------------
__device__ __forceinline__ void mma16816h(float* c, const u32* a, u32 b0, u32 b1) {
    asm volatile(
        "mma.sync.aligned.m16n8k16.row.col.f32.f16.f16.f32 "
        "{%0,%1,%2,%3}, {%4,%5,%6,%7}, {%8,%9}, {%0,%1,%2,%3};"
        : "+f"(c[0]), "+f"(c[1]), "+f"(c[2]), "+f"(c[3])
        : "r"(a[0]), "r"(a[1]), "r"(a[2]), "r"(a[3]), "r"(b0), "r"(b1));
}
__device__ __forceinline__ void ldsm_x4(u32& r0, u32& r1, u32& r2, u32& r3, u32 addr) {
    asm volatile("ldmatrix.sync.aligned.m8n8.x4.shared.b16 {%0,%1,%2,%3}, [%4];"
                 : "=r"(r0), "=r"(r1), "=r"(r2), "=r"(r3) : "r"(addr));
}
__device__ __forceinline__ u32 smem_u32(const void* p) {
    u32 a; asm("{ .reg .u64 t; cvta.to.shared.u64 t, %1; cvt.u32.u64 %0, t; }"
               : "=r"(a) : "l"(p));
    return a;
}

// smem layout for aggregation kernels (byte offsets)
#define SA     72    // alpha row stride (fp16 elems): 144B
#define ST     72    // Ht row stride
#define AG_A   0         // alpha  128 x 144B = 18432
#define AG_HT  18432     // Ht      64 x 144B =  9216
#define AG_ES  27648     // 512 f = 2048
#define AG_ED  29696     // 128 f =  512
#define AG_MSK 30208     // 2048 u32 = 8192
#define AG_ZP  38400     // 256 f = 1024
#define AG_SMEM 39424

// ---------------------------------------------------------------------------
// Kernel A: H1 = x @ W1 (emitted fp16 per-head [b,h,s,f]) + e1 [b,h,s].
// ---------------------------------------------------------------------------
#define HS_STRIDE 264

__global__ void __launch_bounds__(256, 2) kA(const float* __restrict__ x,
                                             const float* __restrict__ W1,
                                             const float* __restrict__ a1s,
                                             const float* __restrict__ a1d) {
    __shared__ __align__(16) float xs[32 * FIN];
    __shared__ __align__(16) float hs[32 * HS_STRIDE];
    __shared__ __align__(16) float av[2 * HF];

    const int b = blockIdx.x, row0 = blockIdx.y * 32;
    const int t = threadIdx.x;

    const float* xp = x + ((size_t)(b * NN + row0)) * FIN;
    for (int i = t; i < 32 * FIN; i += 256) xs[i] = xp[i];
    av[t]      = a1s[t];
    av[t + HF] = a1d[t];

    u64 w1p[32];
#pragma unroll
    for (int kk = 0; kk < 32; kk++)
        w1p[kk] = pack2(W1[(2 * kk) * HF + t], W1[(2 * kk + 1) * HF + t]);
    __syncthreads();

    const int hh = t >> 6, f = t & 63;
    __half* ph = g_B1h + ((size_t)(b * NH + hh) * NN + row0) * HID + f;
    const u64 z2 = pack2(0.f, 0.f);
    for (int r = 0; r < 32; r += 2) {
        const ulonglong2* xr0 = (const ulonglong2*)(xs + r * FIN);
        const ulonglong2* xr1 = (const ulonglong2*)(xs + (r + 1) * FIN);
        u64 aA0 = z2, aB0 = z2, aA1 = z2, aB1 = z2;
#pragma unroll
        for (int q = 0; q < 16; q++) {
            ulonglong2 x0 = xr0[q], x1 = xr1[q];
            ffma2(aA0, x0.x, w1p[2 * q]);
            ffma2(aB0, x0.y, w1p[2 * q + 1]);
            ffma2(aA1, x1.x, w1p[2 * q]);
            ffma2(aB1, x1.y, w1p[2 * q + 1]);
        }
        float2 fa0 = unpack2(aA0), fb0 = unpack2(aB0);
        float2 fa1 = unpack2(aA1), fb1 = unpack2(aB1);
        float acc0 = (fa0.x + fa0.y) + (fb0.x + fb0.y);
        float acc1 = (fa1.x + fa1.y) + (fb1.x + fb1.y);
        hs[r * HS_STRIDE + t]       = acc0;
        hs[(r + 1) * HS_STRIDE + t] = acc1;
        ph[(size_t)r * HID]       = __float2half_rn(acc0);
        ph[(size_t)(r + 1) * HID] = __float2half_rn(acc1);
    }
    __syncthreads();

    {   // e1: thread t -> row = t>>3, h = (t>>1)&3, vec = t&1
        const int row = t >> 3, h = (t >> 1) & 3, vec = t & 1;
        const float4* hp = (const float4*)(hs + row * HS_STRIDE + h * HID);
        const float4* ap = (const float4*)(av + vec * HF + h * HID);
        float s = 0.f;
#pragma unroll
        for (int j = 0; j < 16; j++) {
            float4 hv = hp[j], aw = ap[j];
            s += hv.x * aw.x + hv.y * aw.y + hv.z * aw.z + hv.w * aw.w;
        }
        int idx = (b * NH + h) * NN + row0 + row;
        if (vec == 0) g_E1s[idx] = s; else g_E1d[idx] = s;
    }
}

// ---------------------------------------------------------------------------
// Kernel M: bit-pack adjacency masks. mask[d][s] = adj[s][d]!=0 || d==s.
// ---------------------------------------------------------------------------
__global__ void __launch_bounds__(256) kM(const int* __restrict__ adj) {
    const int b = blockIdx.x, tile = blockIdx.y, d0 = tile * 128;
    const int t = threadIdx.x, lane = t & 31, warp = t >> 5;
    const int* ab = adj + (size_t)b * NN * NN;
    for (int s = warp; s < NN; s += 8) {
#pragma unroll
        for (int w = 0; w < 4; w++) {
            int d = d0 + w * 32 + lane;
            int a = ab[s * NN + d];
            unsigned m = __ballot_sync(0xffffffffu, (a != 0) || (s == d));
            if (lane == 0) g_mask[(((b * 4 + tile) * NN) + s) * 4 + w] = m;
        }
    }
}

// ---------------------------------------------------------------------------
// kAgg1: layer-1 masked-softmax aggregation via single fp16 mma.sync.
// Grid (32, 4 tiles, 4 heads). 256 thr, 3 CTAs/SM (39.4 KB smem).
// ---------------------------------------------------------------------------
__global__ void __launch_bounds__(256, 3) kAgg1(const float* __restrict__ b1) {
    extern __shared__ __align__(16) char sm[];
    float* esS  = (float*)(sm + AG_ES);
    float* edS  = (float*)(sm + AG_ED);
    u32*   mskS = (u32*)  (sm + AG_MSK);
    float* zpS  = (float*)(sm + AG_ZP);
    const u32 smB = smem_u32(sm);

    const int b = blockIdx.x, tile = blockIdx.y, head = blockIdx.z;
    const int d0 = tile * 128;
    const int t = threadIdx.x, lane = t & 31, warp = t >> 5;

    for (int i = t; i < NN; i += 256) esS[i] = g_E1s[(b * NH + head) * NN + i];
    if (t < 128) edS[t] = g_E1d[(b * NH + head) * NN + d0 + t];
    for (int i = t; i < NN * 4; i += 256)
        mskS[i] = g_mask[((b * 4 + tile) * NN) * 4 + i];
    __syncthreads();

    // fill mapping
    const int dF = t >> 1, half = t & 1;
    const float edv = edS[dF];
    const u32 mybit = 1u << (dF & 31);
    const int mw = dF >> 5;
    u32* aF = (u32*)(sm + AG_A + dF * (SA * 2) + half * 64);

    // Ht copy mapping
    const int sH = t >> 2, fg = t & 3;

    // ldmatrix lane addresses
    const int g = lane >> 2, tig = lane & 3;
    const u32 aA = smB + AG_A + (warp * 16 + (lane & 15)) * (SA * 2)
                 + ((lane >> 4) * 16);
    // B pairs: lanes 0-15 -> n-tile nt, lanes 16-31 -> nt+1
    const u32 bBase = smB + AG_HT + (lane & 7) * (ST * 2)
                    + (((lane >> 3) & 1) * 16) + (((lane >> 4) & 1) * (8 * ST * 2));

    float acc[32];
#pragma unroll
    for (int i = 0; i < 32; i++) acc[i] = 0.f;
    float z = 0.f;

    for (int ck = 0; ck < 8; ck++) {
        const int s0 = ck * 64;
        // ---- alpha fill (fp16) ----
#pragma unroll
        for (int i = 0; i < 16; i++) {
            int s = s0 + half * 32 + 2 * i;
            float sc0 = edv + esS[s];
            float sc1 = edv + esS[s + 1];
            sc0 = fmaxf(sc0, 0.2f * sc0);
            sc1 = fmaxf(sc1, 0.2f * sc1);
            float w0 = (mskS[s * 4 + mw] & mybit) ? __expf(sc0) : 0.f;
            float w1 = (mskS[(s + 1) * 4 + mw] & mybit) ? __expf(sc1) : 0.f;
            z += w0 + w1;
            __half2 hp = __floats2half2_rn(w0, w1);
            aF[i] = *(u32*)&hp;
        }
        // ---- Ht copy (transpose to [f][s], stride ST) ----
        {
            const __half* srch =
                g_B1h + ((size_t)(b * NH + head) * NN + s0 + sH) * HID + fg * 16;
            uint4 vh[2];
            vh[0] = ((const uint4*)srch)[0]; vh[1] = ((const uint4*)srch)[1];
            const __half* eh = (const __half*)vh;
            __half* Ht = (__half*)(sm + AG_HT);
#pragma unroll
            for (int j = 0; j < 16; j++) {
                int f = fg * 16 + j;
                Ht[f * ST + sH] = eh[j];
            }
        }
        __syncthreads();

        // ---- mma: 4 ksteps x 8 n-tiles (B in pairs) ----
#pragma unroll
        for (int ks = 0; ks < 4; ks++) {
            u32 a4[4];
            ldsm_x4(a4[0], a4[1], a4[2], a4[3], aA + ks * 32);
#pragma unroll
            for (int nt = 0; nt < 8; nt += 2) {
                u32 b00, b01, b10, b11;
                ldsm_x4(b00, b01, b10, b11, bBase + nt * (8 * ST * 2) + ks * 32);
                mma16816h(acc + nt * 4,     a4, b00, b01);
                mma16816h(acc + nt * 4 + 4, a4, b10, b11);
            }
        }
        __syncthreads();
    }

    // ---- epilogue: Z, normalize, +b1, ELU -> g_T1 ----
    zpS[t] = z;
    __syncthreads();
    const int r0 = warp * 16 + g, r1 = r0 + 8;
    const float rZ0 = 1.0f / (zpS[2 * r0] + zpS[2 * r0 + 1]);
    const float rZ1 = 1.0f / (zpS[2 * r1] + zpS[2 * r1 + 1]);
    float* o0 = g_T1 + ((size_t)(b * NN + d0 + r0)) * HF + head * 64;
    float* o1 = g_T1 + ((size_t)(b * NN + d0 + r1)) * HF + head * 64;
#pragma unroll
    for (int nt = 0; nt < 8; nt++) {
        int cb = nt * 8 + 2 * tig;
        float2 bv = *(const float2*)(b1 + head * 64 + cb);
        float v0 = acc[nt * 4 + 0] * rZ0 + bv.x;
        float v1 = acc[nt * 4 + 1] * rZ0 + bv.y;
        float v2 = acc[nt * 4 + 2] * rZ1 + bv.x;
        float v3 = acc[nt * 4 + 3] * rZ1 + bv.y;
        v0 = v0 > 0.f ? v0 : (__expf(v0) - 1.f);
        v1 = v1 > 0.f ? v1 : (__expf(v1) - 1.f);
        v2 = v2 > 0.f ? v2 : (__expf(v2) - 1.f);
        v3 = v3 > 0.f ? v3 : (__expf(v3) - 1.f);
        *(float2*)(o0 + cb) = make_float2(v0, v1);
        *(float2*)(o1 + cb) = make_float2(v2, v3);
    }
}

// ---------------------------------------------------------------------------
// kP: proj2 with W2 staged through smem (64-row chunks) + e2 + fp16 H2.
// ---------------------------------------------------------------------------
#define H2S_STRIDE 72
#define KP_OFF_W2  32768
#define KP_OFF_H2S 49152
#define KP_SMEM    (49152 + 32 * H2S_STRIDE * 4)

__global__ void __launch_bounds__(256) kP(const float* __restrict__ W2,
                                          const float* __restrict__ a2s,
                                          const float* __restrict__ a2d) {
    extern __shared__ __align__(16) char smp[];
    float* tile = (float*)smp;
    float* w2s  = (float*)(smp + KP_OFF_W2);
    float* h2s  = (float*)(smp + KP_OFF_H2S);
    const int b = blockIdx.x, n0 = blockIdx.y * 32;
    const int t = threadIdx.x;

    const float4* src = (const float4*)(g_T1 + ((size_t)(b * NN + n0)) * HF);
    for (int i = t; i < 32 * HF / 4; i += 256) ((float4*)tile)[i] = src[i];

    const int o = t & 63, grp = t >> 6;
    u64 accA[8], accB[8];
#pragma unroll
    for (int i = 0; i < 8; i++) { accA[i] = pack2(0.f, 0.f); accB[i] = pack2(0.f, 0.f); }

    for (int cc = 0; cc < 4; cc++) {
        if (cc) __syncthreads();
        const float4* wsrc = (const float4*)(W2 + cc * 64 * FOUT);
        for (int i = t; i < 64 * FOUT / 4; i += 256) ((float4*)w2s)[i] = wsrc[i];
        __syncthreads();
#pragma unroll
        for (int cl = 0; cl < 64; cl += 4) {
            const int c = cc * 64 + cl;
            u64 wpA = pack2(w2s[cl * FOUT + o],       w2s[(cl + 1) * FOUT + o]);
            u64 wpB = pack2(w2s[(cl + 2) * FOUT + o], w2s[(cl + 3) * FOUT + o]);
#pragma unroll
            for (int i = 0; i < 8; i++) {
                ulonglong2 tv = *(const ulonglong2*)(tile + (grp * 8 + i) * HF + c);
                ffma2(accA[i], tv.x, wpA);
                ffma2(accB[i], tv.y, wpB);
            }
        }
    }
#pragma unroll
    for (int i = 0; i < 8; i++) {
        float2 va = unpack2(accA[i]), vb = unpack2(accB[i]);
        float v = (va.x + va.y) + (vb.x + vb.y);
        int d = grp * 8 + i;
        size_t gi = ((size_t)(b * NN + n0 + d)) * FOUT + o;
        g_B2h[gi] = __float2half_rn(v);
        h2s[d * H2S_STRIDE + o] = v;
    }
    __syncthreads();

    if (t < 64) {
        const int node = t >> 1, vec = t & 1;
        const float* aw = vec ? a2d : a2s;
        const float4* hp = (const float4*)(h2s + node * H2S_STRIDE);
        float s = 0.f;
#pragma unroll
        for (int j = 0; j < 16; j++) {
            float4 hv = hp[j];
            s += hv.x * aw[4 * j] + hv.y * aw[4 * j + 1]
               + hv.z * aw[4 * j + 2] + hv.w * aw[4 * j + 3];
        }
        int idx = b * NN + n0 + node;
        if (vec == 0) g_E2s[idx] = s; else g_E2d[idx] = s;
    }
}

// ---------------------------------------------------------------------------
// kAgg2: layer-2 aggregation via single fp16 mma.sync + b2 -> out.
// Grid (32, 4, 2): z splits 64 cols into 32-col halves. 3 CTAs/SM.
// ---------------------------------------------------------------------------
__global__ void __launch_bounds__(256, 3) kAgg2(const float* __restrict__ b2,
                                                float* __restrict__ out) {
    extern __shared__ __align__(16) char sm[];
    float* esS  = (float*)(sm + AG_ES);
    float* edS  = (float*)(sm + AG_ED);
    u32*   mskS = (u32*)  (sm + AG_MSK);
    float* zpS  = (float*)(sm + AG_ZP);
    const u32 smB = smem_u32(sm);

    const int b = blockIdx.x, tile = blockIdx.y, ncol0 = blockIdx.z * 32;
    const int d0 = tile * 128;
    const int t = threadIdx.x, lane = t & 31, warp = t >> 5;

    for (int i = t; i < NN; i += 256) esS[i] = g_E2s[b * NN + i];
    if (t < 128) edS[t] = g_E2d[b * NN + d0 + t];
    for (int i = t; i < NN * 4; i += 256)
        mskS[i] = g_mask[((b * 4 + tile) * NN) * 4 + i];
    __syncthreads();

    const int dF = t >> 1, half = t & 1;
    const float edv = edS[dF];
    const u32 mybit = 1u << (dF & 31);
    const int mw = dF >> 5;
    u32* aF = (u32*)(sm + AG_A + dF * (SA * 2) + half * 64);

    const int g = lane >> 2, tig = lane & 3;
    const u32 aA = smB + AG_A + (warp * 16 + (lane & 15)) * (SA * 2)
                 + ((lane >> 4) * 16);
    const u32 bBase = smB + AG_HT + (lane & 7) * (ST * 2)
                    + (((lane >> 3) & 1) * 16) + (((lane >> 4) & 1) * (8 * ST * 2));

    float acc[16];
#pragma unroll
    for (int i = 0; i < 16; i++) acc[i] = 0.f;
    float z = 0.f;

    for (int ck = 0; ck < 8; ck++) {
        const int s0 = ck * 64;
#pragma unroll
        for (int i = 0; i < 16; i++) {
            int s = s0 + half * 32 + 2 * i;
            float sc0 = edv + esS[s];
            float sc1 = edv + esS[s + 1];
            sc0 = fmaxf(sc0, 0.2f * sc0);
            sc1 = fmaxf(sc1, 0.2f * sc1);
            float w0 = (mskS[s * 4 + mw] & mybit) ? __expf(sc0) : 0.f;
            float w1 = (mskS[(s + 1) * 4 + mw] & mybit) ? __expf(sc1) : 0.f;
            z += w0 + w1;
            __half2 hp = __floats2half2_rn(w0, w1);
            aF[i] = *(u32*)&hp;
        }
        if (t < 128) {   // Ht copy: 32 cols (this z-half), 64 s rows
            const int sH2 = t >> 1, fg2 = t & 1;
            const __half* srch =
                g_B2h + ((size_t)(b * NN + s0 + sH2)) * FOUT + ncol0 + fg2 * 16;
            uint4 vh[2];
            vh[0] = ((const uint4*)srch)[0]; vh[1] = ((const uint4*)srch)[1];
            const __half* eh = (const __half*)vh;
            __half* Ht = (__half*)(sm + AG_HT);
#pragma unroll
            for (int j = 0; j < 16; j++) {
                int f = fg2 * 16 + j;
                Ht[f * ST + sH2] = eh[j];
            }
        }
        __syncthreads();

#pragma unroll
        for (int ks = 0; ks < 4; ks++) {
            u32 a4[4];
            ldsm_x4(a4[0], a4[1], a4[2], a4[3], aA + ks * 32);
#pragma unroll
            for (int nt = 0; nt < 4; nt += 2) {
                u32 b00, b01, b10, b11;
                ldsm_x4(b00, b01, b10, b11, bBase + nt * (8 * ST * 2) + ks * 32);
                mma16816h(acc + nt * 4,     a4, b00, b01);
                mma16816h(acc + nt * 4 + 4, a4, b10, b11);
            }
        }
        __syncthreads();
    }

    zpS[t] = z;
    __syncthreads();
    const int r0 = warp * 16 + g, r1 = r0 + 8;
    const float rZ0 = 1.0f / (zpS[2 * r0] + zpS[2 * r0 + 1]);
    const float rZ1 = 1.0f / (zpS[2 * r1] + zpS[2 * r1 + 1]);
    float* o0 = out + ((size_t)(b * NN + d0 + r0)) * FOUT + ncol0;
    float* o1 = out + ((size_t)(b * NN + d0 + r1)) * FOUT + ncol0;
#pragma unroll
    for (int nt = 0; nt < 4; nt++) {
        int cb = nt * 8 + 2 * tig;
        float2 bv = *(const float2*)(b2 + ncol0 + cb);
        *(float2*)(o0 + cb) = make_float2(acc[nt * 4 + 0] * rZ0 + bv.x,
                                          acc[nt * 4 + 1] * rZ0 + bv.y);
        *(float2*)(o1 + cb) = make_float2(acc[nt * 4 + 2] * rZ1 + bv.x,
                                          acc[nt * 4 + 3] * rZ1 + bv.y);
    }
}

// ---------------------------------------------------------------------------
extern "C" void kernel_launch(void* const* d_in, const int* in_sizes, int n_in,
                              void* d_out, int out_size) {
    const float* x   = (const float*)d_in[0];
    const int*   adj = (const int*)  d_in[1];
    const float* W1  = (const float*)d_in[2];
    const float* a1s = (const float*)d_in[3];
    const float* a1d = (const float*)d_in[4];
    const float* b1  = (const float*)d_in[5];
    const float* W2  = (const float*)d_in[6];
    const float* a2s = (const float*)d_in[7];
    const float* a2d = (const float*)d_in[8];
    const float* b2  = (const float*)d_in[9];
    float* out = (float*)d_out;

    cudaFuncSetAttribute(kAgg1, cudaFuncAttributeMaxDynamicSharedMemorySize, AG_SMEM);
    cudaFuncSetAttribute(kAgg2, cudaFuncAttributeMaxDynamicSharedMemorySize, AG_SMEM);
    cudaFuncSetAttribute(kP,    cudaFuncAttributeMaxDynamicSharedMemorySize, KP_SMEM);

    kA   <<<dim3(NB, 16), 256>>>(x, W1, a1s, a1d);
    kM   <<<dim3(NB, 4),  256>>>(adj);
    kAgg1<<<dim3(NB, 4, NH), 256, AG_SMEM>>>(b1);
    kP   <<<dim3(NB, 16), 256, KP_SMEM>>>(W2, a2s, a2d);
    kAgg2<<<dim3(NB, 4, 2), 256, AG_SMEM>>>(b2, out);
}

// round 15
// speedup vs baseline: 2.6048x; 1.3580x over previous
#include <cuda_runtime.h>
#include <cuda_bf16.h>
#include <cuda_fp16.h>
#include <cstdint>

// Problem constants
#define NB   32
#define NN   512
#define FIN  64
#define NH   4
#define HID  64
#define HF   256   // NH*HID
#define FOUT 64

typedef unsigned long long u64;
typedef unsigned int       u32;

// ---------------- scratch (static device arrays; no allocation) -------------
__device__ __half g_B1h[NB * NH * NN * HID];   // H1 fp16, [b,h,s,f]
__device__ __half g_B2h[NB * NN * FOUT];       // H2 fp16, [b,s,f]
__device__ __half g_T1h[NB * NN * HF];         // elu(agg1)+b1, fp16
__device__ u32   g_mask[NB * 4 * NN * 4];      // [b,tile128,s,word4]
__device__ float g_E1s[NB * NH * NN], g_E1d[NB * NH * NN];   // [b,h,s]
__device__ float g_E2s[NB * NN],      g_E2d[NB * NN];

// ---------------- mma.sync m16n8k16 fp16 + ldmatrix --------------------------
__device__ __forceinline__ void mma16816h(float* c, const u32* a, u32 b0, u32 b1) {
    asm volatile(
        "mma.sync.aligned.m16n8k16.row.col.f32.f16.f16.f32 "
        "{%0,%1,%2,%3}, {%4,%5,%6,%7}, {%8,%9}, {%0,%1,%2,%3};"
        : "+f"(c[0]), "+f"(c[1]), "+f"(c[2]), "+f"(c[3])
        : "r"(a[0]), "r"(a[1]), "r"(a[2]), "r"(a[3]), "r"(b0), "r"(b1));
}
__device__ __forceinline__ void ldsm_x4(u32& r0, u32& r1, u32& r2, u32& r3, u32 addr) {
    asm volatile("ldmatrix.sync.aligned.m8n8.x4.shared.b16 {%0,%1,%2,%3}, [%4];"
                 : "=r"(r0), "=r"(r1), "=r"(r2), "=r"(r3) : "r"(addr));
}
__device__ __forceinline__ u32 smem_u32(const void* p) {
    u32 a; asm("{ .reg .u64 t; cvta.to.shared.u64 t, %1; cvt.u32.u64 %0, t; }"
               : "=r"(a) : "l"(p));
    return a;
}
__device__ __forceinline__ void st_half2(__half* p, float x, float y) {
    __half2 v = __floats2half2_rn(x, y);
    *(__half2*)p = v;
}

// smem layout for aggregation kernels (byte offsets)
#define SA     72    // alpha row stride (fp16 elems): 144B
#define ST     72    // Ht row stride
#define AG_A   0         // alpha  128 x 144B = 18432
#define AG_HT  18432     // Ht      64 x 144B =  9216
#define AG_ES  27648     // 512 f = 2048
#define AG_ED  29696     // 128 f =  512
#define AG_MSK 30208     // 2048 u32 = 8192
#define AG_ZP  38400     // 256 f = 1024
#define AG_SMEM 39424

// ---------------------------------------------------------------------------
// Kernel A (tensor): H1 = x @ W1 via fp16 mma, + e1 via shfl reduction.
// Grid (32, 16): batch, 32-row tile. 8 warps: (mrow = w&1)*16 rows,
// head h = w>>1 owns 64 output cols. H1 emitted fp16 [b,h,s,f].
// ---------------------------------------------------------------------------
__global__ void __launch_bounds__(256, 2) kA(const float* __restrict__ x,
                                             const float* __restrict__ W1,
                                             const float* __restrict__ a1s,
                                             const float* __restrict__ a1d) {
    __shared__ __align__(16) __half xA[32 * 72];      // x tile fp16 [row][k]
    __shared__ __align__(16) __half W1t[256 * 72];    // W1^T fp16 [n][k]
    __shared__ float avS[512];                        // a1s | a1d

    const int b = blockIdx.x, row0 = blockIdx.y * 32;
    const int t = threadIdx.x, lane = t & 31, warp = t >> 5;

    const float* xp = x + ((size_t)(b * NN + row0)) * FIN;
    for (int i = t; i < 32 * FIN; i += 256) {
        int r = i >> 6, c = i & 63;
        xA[r * 72 + c] = __float2half_rn(xp[i]);
    }
    avS[t]       = a1s[t];
    avS[t + 256] = a1d[t];
#pragma unroll 8
    for (int k = 0; k < 64; k++)
        W1t[t * 72 + k] = __float2half_rn(W1[k * HF + t]);
    __syncthreads();

    const int g = lane >> 2, tig = lane & 3;
    const int mrow = warp & 1, h = warp >> 1;
    const u32 aAddr = smem_u32(xA) + (mrow * 16 + (lane & 15)) * 144
                    + ((lane >> 4) * 16);
    const u32 bAddr = smem_u32(W1t) + (h * 64 + (lane & 7)) * 144
                    + (((lane >> 3) & 1) * 16) + (((lane >> 4) & 1) * (8 * 144));

    float acc[32];
#pragma unroll
    for (int i = 0; i < 32; i++) acc[i] = 0.f;

#pragma unroll
    for (int ks = 0; ks < 4; ks++) {
        u32 a4[4];
        ldsm_x4(a4[0], a4[1], a4[2], a4[3], aAddr + ks * 32);
#pragma unroll
        for (int nt = 0; nt < 8; nt += 2) {
            u32 b00, b01, b10, b11;
            ldsm_x4(b00, b01, b10, b11, bAddr + nt * (8 * 144) + ks * 32);
            mma16816h(acc + nt * 4,     a4, b00, b01);
            mma16816h(acc + nt * 4 + 4, a4, b10, b11);
        }
    }

    // epilogue: H1 fp16 + e1 partial dots reduced over tig
    const int gr0 = row0 + mrow * 16 + g, gr1 = gr0 + 8;
    __half* p0 = g_B1h + ((size_t)(b * NH + h) * NN + gr0) * HID;
    __half* p1 = g_B1h + ((size_t)(b * NH + h) * NN + gr1) * HID;
    float es0 = 0.f, ed0 = 0.f, es1 = 0.f, ed1 = 0.f;
#pragma unroll
    for (int nt = 0; nt < 8; nt++) {
        int cb = nt * 8 + 2 * tig;
        float asx = avS[h * 64 + cb],       asy = avS[h * 64 + cb + 1];
        float adx = avS[256 + h * 64 + cb], ady = avS[256 + h * 64 + cb + 1];
        es0 += acc[nt * 4 + 0] * asx + acc[nt * 4 + 1] * asy;
        ed0 += acc[nt * 4 + 0] * adx + acc[nt * 4 + 1] * ady;
        es1 += acc[nt * 4 + 2] * asx + acc[nt * 4 + 3] * asy;
        ed1 += acc[nt * 4 + 2] * adx + acc[nt * 4 + 3] * ady;
        st_half2(p0 + cb, acc[nt * 4 + 0], acc[nt * 4 + 1]);
        st_half2(p1 + cb, acc[nt * 4 + 2], acc[nt * 4 + 3]);
    }
#pragma unroll
    for (int off = 1; off <= 2; off <<= 1) {
        es0 += __shfl_xor_sync(0xffffffffu, es0, off);
        ed0 += __shfl_xor_sync(0xffffffffu, ed0, off);
        es1 += __shfl_xor_sync(0xffffffffu, es1, off);
        ed1 += __shfl_xor_sync(0xffffffffu, ed1, off);
    }
    if (tig == 0) {
        int base = (b * NH + h) * NN;
        g_E1s[base + gr0] = es0; g_E1d[base + gr0] = ed0;
        g_E1s[base + gr1] = es1; g_E1d[base + gr1] = ed1;
    }
}

// ---------------------------------------------------------------------------
// Kernel M: bit-pack adjacency masks. mask[d][s] = adj[s][d]!=0 || d==s.
// ---------------------------------------------------------------------------
__global__ void __launch_bounds__(256) kM(const int* __restrict__ adj) {
    const int b = blockIdx.x, tile = blockIdx.y, d0 = tile * 128;
    const int t = threadIdx.x, lane = t & 31, warp = t >> 5;
    const int* ab = adj + (size_t)b * NN * NN;
    for (int s = warp; s < NN; s += 8) {
#pragma unroll
        for (int w = 0; w < 4; w++) {
            int d = d0 + w * 32 + lane;
            int a = ab[s * NN + d];
            unsigned m = __ballot_sync(0xffffffffu, (a != 0) || (s == d));
            if (lane == 0) g_mask[(((b * 4 + tile) * NN) + s) * 4 + w] = m;
        }
    }
}

// ---------------------------------------------------------------------------
// kAgg1: layer-1 masked-softmax aggregation via single fp16 mma.sync.
// Grid (32, 4 tiles, 4 heads). 256 thr, 3 CTAs/SM. Epilogue -> g_T1h fp16.
// ---------------------------------------------------------------------------
__global__ void __launch_bounds__(256, 3) kAgg1(const float* __restrict__ b1) {
    extern __shared__ __align__(16) char sm[];
    float* esS  = (float*)(sm + AG_ES);
    float* edS  = (float*)(sm + AG_ED);
    u32*   mskS = (u32*)  (sm + AG_MSK);
    float* zpS  = (float*)(sm + AG_ZP);
    const u32 smB = smem_u32(sm);

    const int b = blockIdx.x, tile = blockIdx.y, head = blockIdx.z;
    const int d0 = tile * 128;
    const int t = threadIdx.x, lane = t & 31, warp = t >> 5;

    for (int i = t; i < NN; i += 256) esS[i] = g_E1s[(b * NH + head) * NN + i];
    if (t < 128) edS[t] = g_E1d[(b * NH + head) * NN + d0 + t];
    for (int i = t; i < NN * 4; i += 256)
        mskS[i] = g_mask[((b * 4 + tile) * NN) * 4 + i];
    __syncthreads();

    const int dF = t >> 1, half = t & 1;
    const float edv = edS[dF];
    const u32 mybit = 1u << (dF & 31);
    const int mw = dF >> 5;
    u32* aF = (u32*)(sm + AG_A + dF * (SA * 2) + half * 64);

    const int sH = t >> 2, fg = t & 3;
    const int g = lane >> 2, tig = lane & 3;
    const u32 aA = smB + AG_A + (warp * 16 + (lane & 15)) * (SA * 2)
                 + ((lane >> 4) * 16);
    const u32 bBase = smB + AG_HT + (lane & 7) * (ST * 2)
                    + (((lane >> 3) & 1) * 16) + (((lane >> 4) & 1) * (8 * ST * 2));

    float acc[32];
#pragma unroll
    for (int i = 0; i < 32; i++) acc[i] = 0.f;
    float z = 0.f;

    for (int ck = 0; ck < 8; ck++) {
        const int s0 = ck * 64;
#pragma unroll
        for (int i = 0; i < 16; i++) {
            int s = s0 + half * 32 + 2 * i;
            float sc0 = edv + esS[s];
            float sc1 = edv + esS[s + 1];
            sc0 = fmaxf(sc0, 0.2f * sc0);
            sc1 = fmaxf(sc1, 0.2f * sc1);
            float w0 = (mskS[s * 4 + mw] & mybit) ? __expf(sc0) : 0.f;
            float w1 = (mskS[(s + 1) * 4 + mw] & mybit) ? __expf(sc1) : 0.f;
            z += w0 + w1;
            __half2 hp = __floats2half2_rn(w0, w1);
            aF[i] = *(u32*)&hp;
        }
        {
            const __half* srch =
                g_B1h + ((size_t)(b * NH + head) * NN + s0 + sH) * HID + fg * 16;
            uint4 vh[2];
            vh[0] = ((const uint4*)srch)[0]; vh[1] = ((const uint4*)srch)[1];
            const __half* eh = (const __half*)vh;
            __half* Ht = (__half*)(sm + AG_HT);
#pragma unroll
            for (int j = 0; j < 16; j++) {
                int f = fg * 16 + j;
                Ht[f * ST + sH] = eh[j];
            }
        }
        __syncthreads();

#pragma unroll
        for (int ks = 0; ks < 4; ks++) {
            u32 a4[4];
            ldsm_x4(a4[0], a4[1], a4[2], a4[3], aA + ks * 32);
#pragma unroll
            for (int nt = 0; nt < 8; nt += 2) {
                u32 b00, b01, b10, b11;
                ldsm_x4(b00, b01, b10, b11, bBase + nt * (8 * ST * 2) + ks * 32);
                mma16816h(acc + nt * 4,     a4, b00, b01);
                mma16816h(acc + nt * 4 + 4, a4, b10, b11);
            }
        }
        __syncthreads();
    }

    zpS[t] = z;
    __syncthreads();
    const int r0 = warp * 16 + g, r1 = r0 + 8;
    const float rZ0 = 1.0f / (zpS[2 * r0] + zpS[2 * r0 + 1]);
    const float rZ1 = 1.0f / (zpS[2 * r1] + zpS[2 * r1 + 1]);
    __half* o0 = g_T1h + ((size_t)(b * NN + d0 + r0)) * HF + head * 64;
    __half* o1 = g_T1h + ((size_t)(b * NN + d0 + r1)) * HF + head * 64;
#pragma unroll
    for (int nt = 0; nt < 8; nt++) {
        int cb = nt * 8 + 2 * tig;
        float2 bv = *(const float2*)(b1 + head * 64 + cb);
        float v0 = acc[nt * 4 + 0] * rZ0 + bv.x;
        float v1 = acc[nt * 4 + 1] * rZ0 + bv.y;
        float v2 = acc[nt * 4 + 2] * rZ1 + bv.x;
        float v3 = acc[nt * 4 + 3] * rZ1 + bv.y;
        v0 = v0 > 0.f ? v0 : (__expf(v0) - 1.f);
        v1 = v1 > 0.f ? v1 : (__expf(v1) - 1.f);
        v2 = v2 > 0.f ? v2 : (__expf(v2) - 1.f);
        v3 = v3 > 0.f ? v3 : (__expf(v3) - 1.f);
        st_half2(o0 + cb, v0, v1);
        st_half2(o1 + cb, v2, v3);
    }
}

// ---------------------------------------------------------------------------
// kP (tensor): H2 = T1 @ W2 via fp16 mma (K chunked 4x64), + e2 via shfl.
// Grid (32, 4): batch, 128-row tile. 8 warps, each 16 rows x 64 cols.
// ---------------------------------------------------------------------------
__global__ void __launch_bounds__(256, 2) kP(const float* __restrict__ W2,
                                             const float* __restrict__ a2s,
                                             const float* __restrict__ a2d) {
    __shared__ __align__(16) __half Ax[128 * 72];    // T1 chunk [row][k]
    __shared__ __align__(16) __half W2t[64 * 72];    // W2^T chunk [n][k]
    __shared__ float a2S[128];                        // a2s | a2d

    const int b = blockIdx.x, d0 = blockIdx.y * 128;
    const int t = threadIdx.x, lane = t & 31, warp = t >> 5;
    const int g = lane >> 2, tig = lane & 3;

    if (t < 64) { a2S[t] = a2s[t]; a2S[64 + t] = a2d[t]; }

    const u32 aAddr = smem_u32(Ax) + (warp * 16 + (lane & 15)) * 144
                    + ((lane >> 4) * 16);
    const u32 bAddr = smem_u32(W2t) + (lane & 7) * 144
                    + (((lane >> 3) & 1) * 16) + (((lane >> 4) & 1) * (8 * 144));

    float acc[32];
#pragma unroll
    for (int i = 0; i < 32; i++) acc[i] = 0.f;

    for (int cc = 0; cc < 4; cc++) {
        if (cc) __syncthreads();
        // A chunk: copy fp16 T1 rows (cols cc*64..+63) -> stride-72 smem
#pragma unroll
        for (int j = 0; j < 4; j++) {
            int idx = t + j * 256;         // 0..1023 uint4s
            int row = idx >> 3, q = idx & 7;
            const uint4* src = (const uint4*)(g_T1h +
                ((size_t)(b * NN + d0 + row)) * HF + cc * 64);
            *(uint4*)((char*)Ax + row * 144 + q * 16) = src[q];
        }
        // W2t chunk: transpose W2[k][n] -> [n][k]
#pragma unroll
        for (int j = 0; j < 16; j++) {
            int idx = t + j * 256;         // 0..4095
            int k = idx >> 6, n = idx & 63;
            W2t[n * 72 + k] = __float2half_rn(W2[(cc * 64 + k) * FOUT + n]);
        }
        __syncthreads();
#pragma unroll
        for (int ks = 0; ks < 4; ks++) {
            u32 a4[4];
            ldsm_x4(a4[0], a4[1], a4[2], a4[3], aAddr + ks * 32);
#pragma unroll
            for (int nt = 0; nt < 8; nt += 2) {
                u32 b00, b01, b10, b11;
                ldsm_x4(b00, b01, b10, b11, bAddr + nt * (8 * 144) + ks * 32);
                mma16816h(acc + nt * 4,     a4, b00, b01);
                mma16816h(acc + nt * 4 + 4, a4, b10, b11);
            }
        }
    }

    // epilogue: H2 fp16 + e2 via tig-reduction
    const int gr0 = d0 + warp * 16 + g, gr1 = gr0 + 8;
    __half* p0 = g_B2h + ((size_t)(b * NN + gr0)) * FOUT;
    __half* p1 = g_B2h + ((size_t)(b * NN + gr1)) * FOUT;
    float es0 = 0.f, ed0 = 0.f, es1 = 0.f, ed1 = 0.f;
#pragma unroll
    for (int nt = 0; nt < 8; nt++) {
        int cb = nt * 8 + 2 * tig;
        float asx = a2S[cb],      asy = a2S[cb + 1];
        float adx = a2S[64 + cb], ady = a2S[64 + cb + 1];
        es0 += acc[nt * 4 + 0] * asx + acc[nt * 4 + 1] * asy;
        ed0 += acc[nt * 4 + 0] * adx + acc[nt * 4 + 1] * ady;
        es1 += acc[nt * 4 + 2] * asx + acc[nt * 4 + 3] * asy;
        ed1 += acc[nt * 4 + 2] * adx + acc[nt * 4 + 3] * ady;
        st_half2(p0 + cb, acc[nt * 4 + 0], acc[nt * 4 + 1]);
        st_half2(p1 + cb, acc[nt * 4 + 2], acc[nt * 4 + 3]);
    }
#pragma unroll
    for (int off = 1; off <= 2; off <<= 1) {
        es0 += __shfl_xor_sync(0xffffffffu, es0, off);
        ed0 += __shfl_xor_sync(0xffffffffu, ed0, off);
        es1 += __shfl_xor_sync(0xffffffffu, es1, off);
        ed1 += __shfl_xor_sync(0xffffffffu, ed1, off);
    }
    if (tig == 0) {
        g_E2s[b * NN + gr0] = es0; g_E2d[b * NN + gr0] = ed0;
        g_E2s[b * NN + gr1] = es1; g_E2d[b * NN + gr1] = ed1;
    }
}

// ---------------------------------------------------------------------------
// kAgg2: layer-2 aggregation via single fp16 mma.sync + b2 -> out.
// Grid (32, 4, 2): z splits 64 cols into 32-col halves. 3 CTAs/SM.
// ---------------------------------------------------------------------------
__global__ void __launch_bounds__(256, 3) kAgg2(const float* __restrict__ b2,
                                                float* __restrict__ out) {
    extern __shared__ __align__(16) char sm[];
    float* esS  = (float*)(sm + AG_ES);
    float* edS  = (float*)(sm + AG_ED);
    u32*   mskS = (u32*)  (sm + AG_MSK);
    float* zpS  = (float*)(sm + AG_ZP);
    const u32 smB = smem_u32(sm);

    const int b = blockIdx.x, tile = blockIdx.y, ncol0 = blockIdx.z * 32;
    const int d0 = tile * 128;
    const int t = threadIdx.x, lane = t & 31, warp = t >> 5;

    for (int i = t; i < NN; i += 256) esS[i] = g_E2s[b * NN + i];
    if (t < 128) edS[t] = g_E2d[b * NN + d0 + t];
    for (int i = t; i < NN * 4; i += 256)
        mskS[i] = g_mask[((b * 4 + tile) * NN) * 4 + i];
    __syncthreads();

    const int dF = t >> 1, half = t & 1;
    const float edv = edS[dF];
    const u32 mybit = 1u << (dF & 31);
    const int mw = dF >> 5;
    u32* aF = (u32*)(sm + AG_A + dF * (SA * 2) + half * 64);

    const int g = lane >> 2, tig = lane & 3;
    const u32 aA = smB + AG_A + (warp * 16 + (lane & 15)) * (SA * 2)
                 + ((lane >> 4) * 16);
    const u32 bBase = smB + AG_HT + (lane & 7) * (ST * 2)
                    + (((lane >> 3) & 1) * 16) + (((lane >> 4) & 1) * (8 * ST * 2));

    float acc[16];
#pragma unroll
    for (int i = 0; i < 16; i++) acc[i] = 0.f;
    float z = 0.f;

    for (int ck = 0; ck < 8; ck++) {
        const int s0 = ck * 64;
#pragma unroll
        for (int i = 0; i < 16; i++) {
            int s = s0 + half * 32 + 2 * i;
            float sc0 = edv + esS[s];
            float sc1 = edv + esS[s + 1];
            sc0 = fmaxf(sc0, 0.2f * sc0);
            sc1 = fmaxf(sc1, 0.2f * sc1);
            float w0 = (mskS[s * 4 + mw] & mybit) ? __expf(sc0) : 0.f;
            float w1 = (mskS[(s + 1) * 4 + mw] & mybit) ? __expf(sc1) : 0.f;
            z += w0 + w1;
            __half2 hp = __floats2half2_rn(w0, w1);
            aF[i] = *(u32*)&hp;
        }
        if (t < 128) {
            const int sH2 = t >> 1, fg2 = t & 1;
            const __half* srch =
                g_B2h + ((size_t)(b * NN + s0 + sH2)) * FOUT + ncol0 + fg2 * 16;
            uint4 vh[2];
            vh[0] = ((const uint4*)srch)[0]; vh[1] = ((const uint4*)srch)[1];
            const __half* eh = (const __half*)vh;
            __half* Ht = (__half*)(sm + AG_HT);
#pragma unroll
            for (int j = 0; j < 16; j++) {
                int f = fg2 * 16 + j;
                Ht[f * ST + sH2] = eh[j];
            }
        }
        __syncthreads();

#pragma unroll
        for (int ks = 0; ks < 4; ks++) {
            u32 a4[4];
            ldsm_x4(a4[0], a4[1], a4[2], a4[3], aA + ks * 32);
#pragma unroll
            for (int nt = 0; nt < 4; nt += 2) {
                u32 b00, b01, b10, b11;
                ldsm_x4(b00, b01, b10, b11, bBase + nt * (8 * ST * 2) + ks * 32);
                mma16816h(acc + nt * 4,     a4, b00, b01);
                mma16816h(acc + nt * 4 + 4, a4, b10, b11);
            }
        }
        __syncthreads();
    }

    zpS[t] = z;
    __syncthreads();
    const int r0 = warp * 16 + g, r1 = r0 + 8;
    const float rZ0 = 1.0f / (zpS[2 * r0] + zpS[2 * r0 + 1]);
    const float rZ1 = 1.0f / (zpS[2 * r1] + zpS[2 * r1 + 1]);
    float* o0 = out + ((size_t)(b * NN + d0 + r0)) * FOUT + ncol0;
    float* o1 = out + ((size_t)(b * NN + d0 + r1)) * FOUT + ncol0;
#pragma unroll
    for (int nt = 0; nt < 4; nt++) {
        int cb = nt * 8 + 2 * tig;
        float2 bv = *(const float2*)(b2 + ncol0 + cb);
        *(float2*)(o0 + cb) = make_float2(acc[nt * 4 + 0] * rZ0 + bv.x,
                                          acc[nt * 4 + 1] * rZ0 + bv.y);
        *(float2*)(o1 + cb) = make_float2(acc[nt * 4 + 2] * rZ1 + bv.x,
                                          acc[nt * 4 + 3] * rZ1 + bv.y);
    }
}

// ---------------------------------------------------------------------------
extern "C" void kernel_launch(void* const* d_in, const int* in_sizes, int n_in,
                              void* d_out, int out_size) {
    const float* x   = (const float*)d_in[0];
    const int*   adj = (const int*)  d_in[1];
    const float* W1  = (const float*)d_in[2];
    const float* a1s = (const float*)d_in[3];
    const float* a1d = (const float*)d_in[4];
    const float* b1  = (const float*)d_in[5];
    const float* W2  = (const float*)d_in[6];
    const float* a2s = (const float*)d_in[7];
    const float* a2d = (const float*)d_in[8];
    const float* b2  = (const float*)d_in[9];
    float* out = (float*)d_out;

    cudaFuncSetAttribute(kAgg1, cudaFuncAttributeMaxDynamicSharedMemorySize, AG_SMEM);
    cudaFuncSetAttribute(kAgg2, cudaFuncAttributeMaxDynamicSharedMemorySize, AG_SMEM);

    kA   <<<dim3(NB, 16), 256>>>(x, W1, a1s, a1d);
    kM   <<<dim3(NB, 4),  256>>>(adj);
    kAgg1<<<dim3(NB, 4, NH), 256, AG_SMEM>>>(b1);
    kP   <<<dim3(NB, 4),  256>>>(W2, a2s, a2d);
    kAgg2<<<dim3(NB, 4, 2), 256, AG_SMEM>>>(b2, out);
}

// round 17
// speedup vs baseline: 2.7033x; 1.0378x over previous
#include <cuda_runtime.h>
#include <cuda_bf16.h>
#include <cuda_fp16.h>
#include <cstdint>

// Problem constants
#define NB   32
#define NN   512
#define FIN  64
#define NH   4
#define HID  64
#define HF   256   // NH*HID
#define FOUT 64

typedef unsigned long long u64;
typedef unsigned int       u32;

// ---------------- scratch (static device arrays; no allocation) -------------
__device__ __half g_B1h[NB * NH * NN * HID];   // H1 fp16, [b,h,s,f]
__device__ __half g_B2h[NB * NN * FOUT];       // H2 fp16, [b,s,f]
__device__ __half g_T1h[NB * NN * HF];         // elu(agg1)+b1, fp16
__device__ u32   g_mask[NB * 4 * NN * 4];      // [b,tile128,s,word4]
__device__ float g_E1s[NB * NH * NN], g_E1d[NB * NH * NN];   // [b,h,s]
__device__ float g_E2s[NB * NN],      g_E2d[NB * NN];

// ---------------- mma.sync m16n8k16 fp16 + ldmatrix --------------------------
__device__ __forceinline__ void mma16816h(float* c, const u32* a, u32 b0, u32 b1) {
    asm volatile(
        "mma.sync.aligned.m16n8k16.row.col.f32.f16.f16.f32 "
        "{%0,%1,%2,%3}, {%4,%5,%6,%7}, {%8,%9}, {%0,%1,%2,%3};"
        : "+f"(c[0]), "+f"(c[1]), "+f"(c[2]), "+f"(c[3])
        : "r"(a[0]), "r"(a[1]), "r"(a[2]), "r"(a[3]), "r"(b0), "r"(b1));
}
__device__ __forceinline__ void ldsm_x4(u32& r0, u32& r1, u32& r2, u32& r3, u32 addr) {
    asm volatile("ldmatrix.sync.aligned.m8n8.x4.shared.b16 {%0,%1,%2,%3}, [%4];"
                 : "=r"(r0), "=r"(r1), "=r"(r2), "=r"(r3) : "r"(addr));
}
__device__ __forceinline__ void ldsm_x4t(u32& r0, u32& r1, u32& r2, u32& r3, u32 addr) {
    asm volatile("ldmatrix.sync.aligned.m8n8.x4.trans.shared.b16 {%0,%1,%2,%3}, [%4];"
                 : "=r"(r0), "=r"(r1), "=r"(r2), "=r"(r3) : "r"(addr));
}
__device__ __forceinline__ u32 smem_u32(const void* p) {
    u32 a; asm("{ .reg .u64 t; cvta.to.shared.u64 t, %1; cvt.u32.u64 %0, t; }"
               : "=r"(a) : "l"(p));
    return a;
}
__device__ __forceinline__ void st_half2(__half* p, float x, float y) {
    __half2 v = __floats2half2_rn(x, y);
    *(__half2*)p = v;
}

// ---- kAgg1 smem layout: double-buffered [alpha 18432 | H 64x144=9216] ----
#define SA      72       // alpha row stride (halves); 144B = 9*16 aligned
#define HSTR    144      // H row stride (bytes) = 9*16 aligned
#define A1_BUF  27648    // bytes per buffer
#define A1_HOFF 18432
#define A1_ES   55296
#define A1_ED   57344
#define A1_MSK  57856
#define A1_ZP   66048
#define A1_SMEM 67072

// ---- kAgg2 smem layout: double-buffered [alpha 18432 | H 64x80=5120] ----
#define H2STR   80       // 5*16 -> 16B-aligned rows (72 was the misalignment bug)
#define A2_BUF  23552
#define A2_HOFF 18432
#define A2_ES   47104
#define A2_ED   49152
#define A2_MSK  49664
#define A2_ZP   57856
#define A2_SMEM 58880

// ---------------------------------------------------------------------------
// Kernel A (tensor): H1 = x @ W1 via fp16 mma, + e1 via shfl reduction.
// ---------------------------------------------------------------------------
__global__ void __launch_bounds__(256, 2) kA(const float* __restrict__ x,
                                             const float* __restrict__ W1,
                                             const float* __restrict__ a1s,
                                             const float* __restrict__ a1d) {
    __shared__ __align__(16) __half xA[32 * 72];
    __shared__ __align__(16) __half W1t[256 * 72];
    __shared__ float avS[512];

    const int b = blockIdx.x, row0 = blockIdx.y * 32;
    const int t = threadIdx.x, lane = t & 31, warp = t >> 5;

    const float* xp = x + ((size_t)(b * NN + row0)) * FIN;
    for (int i = t; i < 32 * FIN; i += 256) {
        int r = i >> 6, c = i & 63;
        xA[r * 72 + c] = __float2half_rn(xp[i]);
    }
    avS[t]       = a1s[t];
    avS[t + 256] = a1d[t];
#pragma unroll 8
    for (int k = 0; k < 64; k++)
        W1t[t * 72 + k] = __float2half_rn(W1[k * HF + t]);
    __syncthreads();

    const int g = lane >> 2, tig = lane & 3;
    const int mrow = warp & 1, h = warp >> 1;
    const u32 aAddr = smem_u32(xA) + (mrow * 16 + (lane & 15)) * 144
                    + ((lane >> 4) * 16);
    const u32 bAddr = smem_u32(W1t) + (h * 64 + (lane & 7)) * 144
                    + (((lane >> 3) & 1) * 16) + (((lane >> 4) & 1) * (8 * 144));

    float acc[32];
#pragma unroll
    for (int i = 0; i < 32; i++) acc[i] = 0.f;

#pragma unroll
    for (int ks = 0; ks < 4; ks++) {
        u32 a4[4];
        ldsm_x4(a4[0], a4[1], a4[2], a4[3], aAddr + ks * 32);
#pragma unroll
        for (int nt = 0; nt < 8; nt += 2) {
            u32 b00, b01, b10, b11;
            ldsm_x4(b00, b01, b10, b11, bAddr + nt * (8 * 144) + ks * 32);
            mma16816h(acc + nt * 4,     a4, b00, b01);
            mma16816h(acc + nt * 4 + 4, a4, b10, b11);
        }
    }

    const int gr0 = row0 + mrow * 16 + g, gr1 = gr0 + 8;
    __half* p0 = g_B1h + ((size_t)(b * NH + h) * NN + gr0) * HID;
    __half* p1 = g_B1h + ((size_t)(b * NH + h) * NN + gr1) * HID;
    float es0 = 0.f, ed0 = 0.f, es1 = 0.f, ed1 = 0.f;
#pragma unroll
    for (int nt = 0; nt < 8; nt++) {
        int cb = nt * 8 + 2 * tig;
        float asx = avS[h * 64 + cb],       asy = avS[h * 64 + cb + 1];
        float adx = avS[256 + h * 64 + cb], ady = avS[256 + h * 64 + cb + 1];
        es0 += acc[nt * 4 + 0] * asx + acc[nt * 4 + 1] * asy;
        ed0 += acc[nt * 4 + 0] * adx + acc[nt * 4 + 1] * ady;
        es1 += acc[nt * 4 + 2] * asx + acc[nt * 4 + 3] * asy;
        ed1 += acc[nt * 4 + 2] * adx + acc[nt * 4 + 3] * ady;
        st_half2(p0 + cb, acc[nt * 4 + 0], acc[nt * 4 + 1]);
        st_half2(p1 + cb, acc[nt * 4 + 2], acc[nt * 4 + 3]);
    }
#pragma unroll
    for (int off = 1; off <= 2; off <<= 1) {
        es0 += __shfl_xor_sync(0xffffffffu, es0, off);
        ed0 += __shfl_xor_sync(0xffffffffu, ed0, off);
        es1 += __shfl_xor_sync(0xffffffffu, es1, off);
        ed1 += __shfl_xor_sync(0xffffffffu, ed1, off);
    }
    if (tig == 0) {
        int base = (b * NH + h) * NN;
        g_E1s[base + gr0] = es0; g_E1d[base + gr0] = ed0;
        g_E1s[base + gr1] = es1; g_E1d[base + gr1] = ed1;
    }
}

// ---------------------------------------------------------------------------
// Kernel M: bit-pack adjacency masks. mask[d][s] = adj[s][d]!=0 || d==s.
// ---------------------------------------------------------------------------
__global__ void __launch_bounds__(256) kM(const int* __restrict__ adj) {
    const int b = blockIdx.x, tile = blockIdx.y, d0 = tile * 128;
    const int t = threadIdx.x, lane = t & 31, warp = t >> 5;
    const int* ab = adj + (size_t)b * NN * NN;
    for (int s = warp; s < NN; s += 8) {
#pragma unroll
        for (int w = 0; w < 4; w++) {
            int d = d0 + w * 32 + lane;
            int a = ab[s * NN + d];
            unsigned m = __ballot_sync(0xffffffffu, (a != 0) || (s == d));
            if (lane == 0) g_mask[(((b * 4 + tile) * NN) + s) * 4 + w] = m;
        }
    }
}

// ---------------------------------------------------------------------------
// kAgg1: layer-1 aggregation, fp16 mma, double-buffered fill/mma overlap,
// B-fragments via ldmatrix.trans on row-major H. Grid (32,4,NH), 3 CTAs/SM.
// ---------------------------------------------------------------------------
__global__ void __launch_bounds__(256, 3) kAgg1(const float* __restrict__ b1) {
    extern __shared__ __align__(16) char sm[];
    float* esS  = (float*)(sm + A1_ES);
    float* edS  = (float*)(sm + A1_ED);
    u32*   mskS = (u32*)  (sm + A1_MSK);
    float* zpS  = (float*)(sm + A1_ZP);
    const u32 smB = smem_u32(sm);

    const int b = blockIdx.x, tile = blockIdx.y, head = blockIdx.z;
    const int d0 = tile * 128;
    const int t = threadIdx.x, lane = t & 31, warp = t >> 5;

    for (int i = t; i < NN; i += 256) esS[i] = g_E1s[(b * NH + head) * NN + i];
    if (t < 128) edS[t] = g_E1d[(b * NH + head) * NN + d0 + t];
    for (int i = t; i < NN * 4; i += 256)
        mskS[i] = g_mask[((b * 4 + tile) * NN) * 4 + i];
    __syncthreads();

    const int dF = t >> 1, half = t & 1;
    const float edv = edS[dF];
    const u32 mybit = 1u << (dF & 31);
    const int mw = dF >> 5;
    const int aFoff = dF * (SA * 2) + half * 64;      // within alpha region

    const int g = lane >> 2, tig = lane & 3;
    const int aOff = (warp * 16 + (lane & 15)) * (SA * 2) + ((lane >> 4) * 16);
    const int bOff = A1_HOFF + (((lane >> 3) & 1) * 8 + (lane & 7)) * HSTR
                   + (((lane >> 4) & 1) * 16);

    const __half* Hsrc = g_B1h + ((size_t)(b * NH + head) * NN) * HID;

    float acc[32];
#pragma unroll
    for (int i = 0; i < 32; i++) acc[i] = 0.f;
    float z = 0.f;

#define FILL1(ck)                                                             \
    {                                                                         \
        char* base = sm + ((ck) & 1) * A1_BUF;                                \
        u32* aFb = (u32*)(base + aFoff);                                      \
        const int s0f = (ck) * 64;                                            \
        _Pragma("unroll")                                                     \
        for (int i = 0; i < 16; i++) {                                        \
            int s = s0f + half * 32 + 2 * i;                                  \
            float sc0 = edv + esS[s];                                         \
            float sc1 = edv + esS[s + 1];                                     \
            sc0 = fmaxf(sc0, 0.2f * sc0);                                     \
            sc1 = fmaxf(sc1, 0.2f * sc1);                                     \
            float w0 = (mskS[s * 4 + mw] & mybit) ? __expf(sc0) : 0.f;        \
            float w1 = (mskS[(s + 1) * 4 + mw] & mybit) ? __expf(sc1) : 0.f;  \
            z += w0 + w1;                                                     \
            __half2 hp = __floats2half2_rn(w0, w1);                           \
            aFb[i] = *(u32*)&hp;                                              \
        }                                                                     \
        char* Hb = base + A1_HOFF;                                            \
        _Pragma("unroll")                                                     \
        for (int j = 0; j < 2; j++) {                                         \
            int idx = t + j * 256;                                            \
            int row = idx >> 3, q = idx & 7;                                  \
            const uint4* src = (const uint4*)(Hsrc + (size_t)(s0f + row) * HID); \
            *(uint4*)(Hb + row * HSTR + q * 16) = src[q];                     \
        }                                                                     \
    }

    FILL1(0);
    __syncthreads();

    for (int ck = 0; ck < 8; ck++) {
        if (ck < 7) FILL1(ck + 1);
        const u32 bufB = smB + (ck & 1) * A1_BUF;
        const u32 aA = bufB + aOff;
        const u32 bB = bufB + bOff;
#pragma unroll
        for (int ks = 0; ks < 4; ks++) {
            u32 a4[4];
            ldsm_x4(a4[0], a4[1], a4[2], a4[3], aA + ks * 32);
#pragma unroll
            for (int nt = 0; nt < 8; nt += 2) {
                u32 b00, b01, b10, b11;
                ldsm_x4t(b00, b01, b10, b11, bB + ks * (16 * HSTR) + nt * 16);
                mma16816h(acc + nt * 4,     a4, b00, b01);
                mma16816h(acc + nt * 4 + 4, a4, b10, b11);
            }
        }
        __syncthreads();
    }
#undef FILL1

    zpS[t] = z;
    __syncthreads();
    const int r0 = warp * 16 + g, r1 = r0 + 8;
    const float rZ0 = 1.0f / (zpS[2 * r0] + zpS[2 * r0 + 1]);
    const float rZ1 = 1.0f / (zpS[2 * r1] + zpS[2 * r1 + 1]);
    __half* o0 = g_T1h + ((size_t)(b * NN + d0 + r0)) * HF + head * 64;
    __half* o1 = g_T1h + ((size_t)(b * NN + d0 + r1)) * HF + head * 64;
#pragma unroll
    for (int nt = 0; nt < 8; nt++) {
        int cb = nt * 8 + 2 * tig;
        float2 bv = *(const float2*)(b1 + head * 64 + cb);
        float v0 = acc[nt * 4 + 0] * rZ0 + bv.x;
        float v1 = acc[nt * 4 + 1] * rZ0 + bv.y;
        float v2 = acc[nt * 4 + 2] * rZ1 + bv.x;
        float v3 = acc[nt * 4 + 3] * rZ1 + bv.y;
        v0 = v0 > 0.f ? v0 : (__expf(v0) - 1.f);
        v1 = v1 > 0.f ? v1 : (__expf(v1) - 1.f);
        v2 = v2 > 0.f ? v2 : (__expf(v2) - 1.f);
        v3 = v3 > 0.f ? v3 : (__expf(v3) - 1.f);
        st_half2(o0 + cb, v0, v1);
        st_half2(o1 + cb, v2, v3);
    }
}

// ---------------------------------------------------------------------------
// kP (tensor): H2 = T1 @ W2 via fp16 mma (K chunked 4x64), + e2 via shfl.
// ---------------------------------------------------------------------------
__global__ void __launch_bounds__(256, 2) kP(const float* __restrict__ W2,
                                             const float* __restrict__ a2s,
                                             const float* __restrict__ a2d) {
    __shared__ __align__(16) __half Ax[128 * 72];
    __shared__ __align__(16) __half W2t[64 * 72];
    __shared__ float a2S[128];

    const int b = blockIdx.x, d0 = blockIdx.y * 128;
    const int t = threadIdx.x, lane = t & 31, warp = t >> 5;
    const int g = lane >> 2, tig = lane & 3;

    if (t < 64) { a2S[t] = a2s[t]; a2S[64 + t] = a2d[t]; }

    const u32 aAddr = smem_u32(Ax) + (warp * 16 + (lane & 15)) * 144
                    + ((lane >> 4) * 16);
    const u32 bAddr = smem_u32(W2t) + (lane & 7) * 144
                    + (((lane >> 3) & 1) * 16) + (((lane >> 4) & 1) * (8 * 144));

    float acc[32];
#pragma unroll
    for (int i = 0; i < 32; i++) acc[i] = 0.f;

    for (int cc = 0; cc < 4; cc++) {
        if (cc) __syncthreads();
#pragma unroll
        for (int j = 0; j < 4; j++) {
            int idx = t + j * 256;
            int row = idx >> 3, q = idx & 7;
            const uint4* src = (const uint4*)(g_T1h +
                ((size_t)(b * NN + d0 + row)) * HF + cc * 64);
            *(uint4*)((char*)Ax + row * 144 + q * 16) = src[q];
        }
#pragma unroll
        for (int j = 0; j < 16; j++) {
            int idx = t + j * 256;
            int k = idx >> 6, n = idx & 63;
            W2t[n * 72 + k] = __float2half_rn(W2[(cc * 64 + k) * FOUT + n]);
        }
        __syncthreads();
#pragma unroll
        for (int ks = 0; ks < 4; ks++) {
            u32 a4[4];
            ldsm_x4(a4[0], a4[1], a4[2], a4[3], aAddr + ks * 32);
#pragma unroll
            for (int nt = 0; nt < 8; nt += 2) {
                u32 b00, b01, b10, b11;
                ldsm_x4(b00, b01, b10, b11, bAddr + nt * (8 * 144) + ks * 32);
                mma16816h(acc + nt * 4,     a4, b00, b01);
                mma16816h(acc + nt * 4 + 4, a4, b10, b11);
            }
        }
    }

    const int gr0 = d0 + warp * 16 + g, gr1 = gr0 + 8;
    __half* p0 = g_B2h + ((size_t)(b * NN + gr0)) * FOUT;
    __half* p1 = g_B2h + ((size_t)(b * NN + gr1)) * FOUT;
    float es0 = 0.f, ed0 = 0.f, es1 = 0.f, ed1 = 0.f;
#pragma unroll
    for (int nt = 0; nt < 8; nt++) {
        int cb = nt * 8 + 2 * tig;
        float asx = a2S[cb],      asy = a2S[cb + 1];
        float adx = a2S[64 + cb], ady = a2S[64 + cb + 1];
        es0 += acc[nt * 4 + 0] * asx + acc[nt * 4 + 1] * asy;
        ed0 += acc[nt * 4 + 0] * adx + acc[nt * 4 + 1] * ady;
        es1 += acc[nt * 4 + 2] * asx + acc[nt * 4 + 3] * asy;
        ed1 += acc[nt * 4 + 2] * adx + acc[nt * 4 + 3] * ady;
        st_half2(p0 + cb, acc[nt * 4 + 0], acc[nt * 4 + 1]);
        st_half2(p1 + cb, acc[nt * 4 + 2], acc[nt * 4 + 3]);
    }
#pragma unroll
    for (int off = 1; off <= 2; off <<= 1) {
        es0 += __shfl_xor_sync(0xffffffffu, es0, off);
        ed0 += __shfl_xor_sync(0xffffffffu, ed0, off);
        es1 += __shfl_xor_sync(0xffffffffu, es1, off);
        ed1 += __shfl_xor_sync(0xffffffffu, ed1, off);
    }
    if (tig == 0) {
        g_E2s[b * NN + gr0] = es0; g_E2d[b * NN + gr0] = ed0;
        g_E2s[b * NN + gr1] = es1; g_E2d[b * NN + gr1] = ed1;
    }
}

// ---------------------------------------------------------------------------
// kAgg2: layer-2 aggregation, double-buffered, ldmatrix.trans B.
// Grid (32, 4, 2): z = 32-col half. 3 CTAs/SM.
// ---------------------------------------------------------------------------
__global__ void __launch_bounds__(256, 3) kAgg2(const float* __restrict__ b2,
                                                float* __restrict__ out) {
    extern __shared__ __align__(16) char sm[];
    float* esS  = (float*)(sm + A2_ES);
    float* edS  = (float*)(sm + A2_ED);
    u32*   mskS = (u32*)  (sm + A2_MSK);
    float* zpS  = (float*)(sm + A2_ZP);
    const u32 smB = smem_u32(sm);

    const int b = blockIdx.x, tile = blockIdx.y, ncol0 = blockIdx.z * 32;
    const int d0 = tile * 128;
    const int t = threadIdx.x, lane = t & 31, warp = t >> 5;

    for (int i = t; i < NN; i += 256) esS[i] = g_E2s[b * NN + i];
    if (t < 128) edS[t] = g_E2d[b * NN + d0 + t];
    for (int i = t; i < NN * 4; i += 256)
        mskS[i] = g_mask[((b * 4 + tile) * NN) * 4 + i];
    __syncthreads();

    const int dF = t >> 1, half = t & 1;
    const float edv = edS[dF];
    const u32 mybit = 1u << (dF & 31);
    const int mw = dF >> 5;
    const int aFoff = dF * (SA * 2) + half * 64;

    const int g = lane >> 2, tig = lane & 3;
    const int aOff = (warp * 16 + (lane & 15)) * (SA * 2) + ((lane >> 4) * 16);
    const int bOff = A2_HOFF + (((lane >> 3) & 1) * 8 + (lane & 7)) * H2STR
                   + (((lane >> 4) & 1) * 16);

    const __half* Hsrc = g_B2h + ((size_t)(b * NN)) * FOUT + ncol0;

    float acc[16];
#pragma unroll
    for (int i = 0; i < 16; i++) acc[i] = 0.f;
    float z = 0.f;

#define FILL2(ck)                                                             \
    {                                                                         \
        char* base = sm + ((ck) & 1) * A2_BUF;                                \
        u32* aFb = (u32*)(base + aFoff);                                      \
        const int s0f = (ck) * 64;                                            \
        _Pragma("unroll")                                                     \
        for (int i = 0; i < 16; i++) {                                        \
            int s = s0f + half * 32 + 2 * i;                                  \
            float sc0 = edv + esS[s];                                         \
            float sc1 = edv + esS[s + 1];                                     \
            sc0 = fmaxf(sc0, 0.2f * sc0);                                     \
            sc1 = fmaxf(sc1, 0.2f * sc1);                                     \
            float w0 = (mskS[s * 4 + mw] & mybit) ? __expf(sc0) : 0.f;        \
            float w1 = (mskS[(s + 1) * 4 + mw] & mybit) ? __expf(sc1) : 0.f;  \
            z += w0 + w1;                                                     \
            __half2 hp = __floats2half2_rn(w0, w1);                           \
            aFb[i] = *(u32*)&hp;                                              \
        }                                                                     \
        char* Hb = base + A2_HOFF;                                            \
        {                                                                     \
            int row = t >> 2, q = t & 3;                                      \
            const uint4* src = (const uint4*)(Hsrc + (size_t)(s0f + row) * FOUT); \
            *(uint4*)(Hb + row * H2STR + q * 16) = src[q];                    \
        }                                                                     \
    }

    FILL2(0);
    __syncthreads();

    for (int ck = 0; ck < 8; ck++) {
        if (ck < 7) FILL2(ck + 1);
        const u32 bufB = smB + (ck & 1) * A2_BUF;
        const u32 aA = bufB + aOff;
        const u32 bB = bufB + bOff;
#pragma unroll
        for (int ks = 0; ks < 4; ks++) {
            u32 a4[4];
            ldsm_x4(a4[0], a4[1], a4[2], a4[3], aA + ks * 32);
#pragma unroll
            for (int nt = 0; nt < 4; nt += 2) {
                u32 b00, b01, b10, b11;
                ldsm_x4t(b00, b01, b10, b11, bB + ks * (16 * H2STR) + nt * 16);
                mma16816h(acc + nt * 4,     a4, b00, b01);
                mma16816h(acc + nt * 4 + 4, a4, b10, b11);
            }
        }
        __syncthreads();
    }
#undef FILL2

    zpS[t] = z;
    __syncthreads();
    const int r0 = warp * 16 + g, r1 = r0 + 8;
    const float rZ0 = 1.0f / (zpS[2 * r0] + zpS[2 * r0 + 1]);
    const float rZ1 = 1.0f / (zpS[2 * r1] + zpS[2 * r1 + 1]);
    float* o0 = out + ((size_t)(b * NN + d0 + r0)) * FOUT + ncol0;
    float* o1 = out + ((size_t)(b * NN + d0 + r1)) * FOUT + ncol0;
#pragma unroll
    for (int nt = 0; nt < 4; nt++) {
        int cb = nt * 8 + 2 * tig;
        float2 bv = *(const float2*)(b2 + ncol0 + cb);
        *(float2*)(o0 + cb) = make_float2(acc[nt * 4 + 0] * rZ0 + bv.x,
                                          acc[nt * 4 + 1] * rZ0 + bv.y);
        *(float2*)(o1 + cb) = make_float2(acc[nt * 4 + 2] * rZ1 + bv.x,
                                          acc[nt * 4 + 3] * rZ1 + bv.y);
    }
}

// ---------------------------------------------------------------------------
extern "C" void kernel_launch(void* const* d_in, const int* in_sizes, int n_in,
                              void* d_out, int out_size) {
    const float* x   = (const float*)d_in[0];
    const int*   adj = (const int*)  d_in[1];
    const float* W1  = (const float*)d_in[2];
    const float* a1s = (const float*)d_in[3];
    const float* a1d = (const float*)d_in[4];
    const float* b1  = (const float*)d_in[5];
    const float* W2  = (const float*)d_in[6];
    const float* a2s = (const float*)d_in[7];
    const float* a2d = (const float*)d_in[8];
    const float* b2  = (const float*)d_in[9];
    float* out = (float*)d_out;

    cudaFuncSetAttribute(kAgg1, cudaFuncAttributeMaxDynamicSharedMemorySize, A1_SMEM);
    cudaFuncSetAttribute(kAgg2, cudaFuncAttributeMaxDynamicSharedMemorySize, A2_SMEM);

    kA   <<<dim3(NB, 16), 256>>>(x, W1, a1s, a1d);
    kM   <<<dim3(NB, 4),  256>>>(adj);
    kAgg1<<<dim3(NB, 4, NH), 256, A1_SMEM>>>(b1);
    kP   <<<dim3(NB, 4),  256>>>(W2, a2s, a2d);
    kAgg2<<<dim3(NB, 4, 2), 256, A2_SMEM>>>(b2, out);
}